// round 8
// baseline (speedup 1.0000x reference)
#include <cuda_runtime.h>
#include <cuda_fp16.h>
#include <cstdint>

#define NN     256
#define NPIX   65536
#define CIN    192
#define COUT   192
#define NCHUNK 27
#define STG    57344          // stage: A 32K | B 24K

// ---------------- device scratch ----------------
__device__ float g_Wsum[COUT * CIN];     // per-(OC,IC) sum over taps
__device__ float g_meanin[CIN];
__device__ float g_add[COUT];
__device__ float g_psum[3 * 64 * 512];   // per-block channel partial sums
__device__ __align__(1024) __half g_Wh[(size_t)NCHUNK * 12288];  // [chunk] 192x64 fp16 swizzled
__device__ __align__(16) uint32_t g_xh[(size_t)3 * NPIX * 32];   // [c][pix][k2] fp16 pairs

// ---------------- helpers ----------------
__device__ __forceinline__ uint32_t smem_u32(const void* p) {
    uint32_t a;
    asm("{ .reg .u64 t; cvta.to.shared.u64 t, %1; cvt.u32.u64 %0, t; }" : "=r"(a) : "l"(p));
    return a;
}
__device__ __forceinline__ uint32_t swz(uint32_t off) { return off ^ ((off >> 3) & 0x70); }
__device__ __forceinline__ void ldsm4(uint32_t* r, uint32_t addr) {
    asm volatile("ldmatrix.sync.aligned.m8n8.x4.shared.b16 {%0,%1,%2,%3}, [%4];"
                 : "=r"(r[0]), "=r"(r[1]), "=r"(r[2]), "=r"(r[3]) : "r"(addr));
}
__device__ __forceinline__ void mma16816(float* d, const uint32_t* a, const uint32_t* b) {
    asm volatile("mma.sync.aligned.m16n8k16.row.col.f32.f16.f16.f32 "
                 "{%0,%1,%2,%3}, {%4,%5,%6,%7}, {%8,%9}, {%0,%1,%2,%3};"
                 : "+f"(d[0]), "+f"(d[1]), "+f"(d[2]), "+f"(d[3])
                 : "r"(a[0]), "r"(a[1]), "r"(a[2]), "r"(a[3]), "r"(b[0]), "r"(b[1]));
}
__device__ __forceinline__ void cpa16(uint32_t dst, const void* src) {
    asm volatile("cp.async.cg.shared.global [%0], [%1], 16;" :: "r"(dst), "l"(src));
}

// ================= launch 0: weight synthesis -> fp16 tiles + tap-sums =================
__global__ void k_weights(const float* __restrict__ fil0, const float* __restrict__ fil1,
                          const float* __restrict__ fil2, const float* __restrict__ w00,
                          const float* __restrict__ w01, const float* __restrict__ w10,
                          const float* __restrict__ w11) {
    int idx = blockIdx.x * blockDim.x + threadIdx.x;
    if (idx >= COUT * CIN) return;
    int OC = idx / CIN, IC = idx % CIN;
    float acc[9];
#pragma unroll
    for (int t = 0; t < 9; t++) acc[t] = 0.f;
    if (OC < 64) {
        if (IC < 64) {
            for (int k = 0; k < 3; k++) {
                float c = w00[(OC * 64 + IC) * 3 + k];
#pragma unroll
                for (int t = 0; t < 9; t++) acc[t] += c * fil0[k * 9 + t];
            }
        } else {
            int ici = (IC - 64) >> 1, tin = (IC - 64) & 1;
            for (int k = 0; k < 6; k++) {
                float c = w10[(OC * 64 + ici) * 6 + k];
#pragma unroll
                for (int t = 0; t < 9; t++) acc[t] += c * fil1[(k * 9 + t) * 2 + tin];
            }
        }
    } else {
        int oco = (OC - 64) >> 1, tout = (OC - 64) & 1;
        if (IC < 64) {
            for (int k = 0; k < 6; k++) {
                float c = w01[(oco * 64 + IC) * 6 + k];
#pragma unroll
                for (int t = 0; t < 9; t++) acc[t] += c * fil1[(k * 9 + t) * 2 + tout];
            }
        } else {
            int ici = (IC - 64) >> 1, tin = (IC - 64) & 1;
            for (int k = 0; k < 12; k++) {
                float c = w11[(oco * 64 + ici) * 12 + k];
#pragma unroll
                for (int t = 0; t < 9; t++) acc[t] += c * fil2[((k * 9 + t) * 2 + tin) * 2 + tout];
            }
        }
    }
    float s = 0.f;
    int cg = IC >> 6, kk = IC & 63;
    uint32_t sw = swz((uint32_t)(OC * 128 + kk * 2)) >> 1;
#pragma unroll
    for (int t = 0; t < 9; t++) {
        s += acc[t];
        g_Wh[(size_t)(t * 3 + cg) * 12288 + sw] = __float2half_rn(acc[t]);
    }
    g_Wsum[idx] = s;
}

// ================= launch 1: x -> pixel-major fp16 planes + partial channel sums =================
#define XS 36   // smem row stride in words (144 B)
__global__ void k_xpack(const float* __restrict__ x0, const float* __restrict__ x1) {
    __shared__ uint32_t shh[128 * XS];
    __shared__ float red[64][2];
    const int c = blockIdx.y, tid = threadIdx.x;
    const int px = blockIdx.x * 128 + tid;
#pragma unroll 4
    for (int k2 = 0; k2 < 32; k2++) {
        float v0, v1;
        if (c == 0) {
            v0 = x0[(size_t)(2 * k2) * NPIX + px];
            v1 = x0[(size_t)(2 * k2 + 1) * NPIX + px];
        } else {
            int j = (c - 1) * 64 + 2 * k2;
            float2 p = *(const float2*)&x1[((size_t)(j >> 1) * NPIX + px) * 2];
            v0 = p.x; v1 = p.y;
        }
        __half h0 = __float2half_rn(v0), h1 = __float2half_rn(v1);
        shh[tid * XS + k2] = (uint32_t)__half_as_ushort(h0) | ((uint32_t)__half_as_ushort(h1) << 16);
    }
    __syncthreads();
    // coalesced write of 128B pixel records
#pragma unroll
    for (int r = 0; r < 8; r++) {
        int s = tid + 128 * r;
        int pl = s >> 3, q = s & 7;
        uint4 vh = *(const uint4*)&shh[pl * XS + q * 4];
        size_t o = ((size_t)c * NPIX + blockIdx.x * 128 + pl) * 32 + q * 4;
        *(uint4*)&g_xh[o] = vh;
    }
    // per-channel partial sums over this block's 128 pixels (from fp16 staging)
    {
        int ch = tid & 63, seg = tid >> 6;      // 2 pixel segments of 64
        int k2 = ch >> 1, half = ch & 1;
        float s = 0.f;
        for (int p = 0; p < 64; p++) {
            uint32_t w = shh[(seg * 64 + p) * XS + k2];
            s += __half2float(__ushort_as_half((unsigned short)(half ? (w >> 16) : (w & 0xFFFF))));
        }
        red[ch][seg] = s;
        __syncthreads();
        if (tid < 64)
            g_psum[(c * 64 + tid) * 512 + blockIdx.x] = red[tid][0] + red[tid][1];
    }
}

// ================= launch 2: reduce channel means =================
__global__ void k_meanred() {
    __shared__ float sm[128];
    int ch = blockIdx.x;
    float s = 0.f;
    for (int i = threadIdx.x; i < 512; i += 128) s += g_psum[ch * 512 + i];
    sm[threadIdx.x] = s;
    __syncthreads();
    for (int o = 64; o > 0; o >>= 1) {
        if (threadIdx.x < o) sm[threadIdx.x] += sm[threadIdx.x + o];
        __syncthreads();
    }
    if (threadIdx.x == 0) g_meanin[ch] = sm[0] * (1.f / NPIX);
}

// ================= launch 3: per-OC additive const =================
__global__ void k_addconst(const float* __restrict__ b0, const float* __restrict__ b1) {
    __shared__ float sm[256];
    int OC = blockIdx.x, tid = threadIdx.x;
    float s = 0.f;
    if (tid < CIN) s = g_Wsum[OC * CIN + tid] * g_meanin[tid];
    sm[tid] = s;
    __syncthreads();
    for (int o = 128; o > 0; o >>= 1) {
        if (tid < o) sm[tid] += sm[tid + o];
        __syncthreads();
    }
    if (tid == 0) g_add[OC] = (OC < 64) ? b0[OC] : sm[0] * b1[(OC - 64) >> 1];
}

// ================= launch 4: conv = implicit GEMM, M=256/CTA, 3-stage =================
// 256 CTAs (one image row each), 512 thr = 16 warps (8M x 2N).
__global__ __launch_bounds__(512, 1) void k_conv(float* __restrict__ out) {
    extern __shared__ __align__(1024) char smem[];
    const uint32_t sb = smem_u32(smem);
    const int tid = threadIdx.x;
    const int lane = tid & 31, warp = tid >> 5;
    const int wm = warp & 7, wn = warp >> 3;
    const int y = blockIdx.x;

    const int a_row = (lane & 7) + ((lane >> 3) & 1) * 8;
    const int a_ks  = lane >> 4;
    const int b_row = (lane & 7) + ((lane >> 4) << 3);
    const int b_ks  = (lane >> 3) & 1;

    const int am = tid >> 1;         // A row loaded by this thread (0..255)
    const int aq = (tid & 1) * 4;    // first 16B chunk (0 or 4)

    float acc[2][12][4];
#pragma unroll
    for (int t = 0; t < 2; t++)
#pragma unroll
        for (int g = 0; g < 12; g++)
#pragma unroll
            for (int q = 0; q < 4; q++) acc[t][g][q] = 0.f;

#define ISSUE(I, S)                                                                  \
    {                                                                                \
        int tap = (I) / 3, c = (I) % 3;                                              \
        int ky = tap / 3, kx = tap % 3;                                              \
        int gy = (y + ky + 255) & 255;                                               \
        int gx = (am + kx + 255) & 255;                                              \
        size_t so = ((size_t)((c << 16) + (gy << 8) + gx)) * 128 + (size_t)(aq * 16);\
        _Pragma("unroll")                                                            \
        for (int j = 0; j < 4; j++) {                                                \
            uint32_t d = sb + (S) * STG + swz((uint32_t)(am * 128 + (aq + j) * 16)); \
            cpa16(d, (const char*)g_xh + so + j * 16);                               \
        }                                                                            \
        const char* bs = (const char*)g_Wh + (size_t)(I) * 24576;                    \
        _Pragma("unroll")                                                            \
        for (int j = 0; j < 3; j++) {                                                \
            int off = (tid + 512 * j) * 16;                                          \
            cpa16(sb + (S) * STG + 32768 + off, bs + off);                           \
        }                                                                            \
        asm volatile("cp.async.commit_group;");                                      \
    }

    ISSUE(0, 0);
    ISSUE(1, 1);

#pragma unroll 3
    for (int i = 0; i < NCHUNK; i++) {
        if (i < NCHUNK - 2) { asm volatile("cp.async.wait_group 1;" ::: "memory"); }
        else                { asm volatile("cp.async.wait_group 0;" ::: "memory"); }
        __syncthreads();
        if (i + 2 < NCHUNK) ISSUE(i + 2, (i + 2) % 3);

        const uint32_t Ab = sb + (i % 3) * STG;
        const uint32_t Bb = Ab + 32768;
#pragma unroll
        for (int ks = 0; ks < 4; ks++) {
            uint32_t ah[2][4];
#pragma unroll
            for (int t = 0; t < 2; t++) {
                uint32_t off = swz((uint32_t)((wm * 32 + t * 16 + a_row) * 128 + ks * 32 + a_ks * 16));
                ldsm4(ah[t], Ab + off);
            }
#pragma unroll
            for (int g = 0; g < 6; g++) {
                uint32_t offb = swz((uint32_t)((wn * 96 + g * 16 + b_row) * 128 + ks * 32 + b_ks * 16));
                uint32_t bh[4];
                ldsm4(bh, Bb + offb);
#pragma unroll
                for (int t = 0; t < 2; t++) {
#pragma unroll
                    for (int h = 0; h < 2; h++) {
                        mma16816(acc[t][g * 2 + h], ah[t], bh + 2 * h);
                    }
                }
            }
        }
    }
#undef ISSUE

    // ---- epilogue ----
    const int col = (lane & 3) * 2;
    const int rowq = lane >> 2;
#pragma unroll
    for (int t = 0; t < 2; t++) {
        int px0 = wm * 32 + t * 16 + rowq;
        int px1 = px0 + 8;
#pragma unroll
        for (int nf = 0; nf < 12; nf++) {
            int n = wn * 96 + nf * 8 + col;
            float g0 = __ldg(&g_add[n]), g1 = __ldg(&g_add[n + 1]);
            float v0 = acc[t][nf][0] + g0, v1 = acc[t][nf][1] + g1;
            float v2 = acc[t][nf][2] + g0, v3 = acc[t][nf][3] + g1;
            if (n < 64) {
                out[(size_t)n * NPIX + y * NN + px0]       = v0;
                out[(size_t)(n + 1) * NPIX + y * NN + px0] = v1;
                out[(size_t)n * NPIX + y * NN + px1]       = v2;
                out[(size_t)(n + 1) * NPIX + y * NN + px1] = v3;
            } else {
                int oco = (n - 64) >> 1;
                size_t base = (size_t)64 * NPIX + ((size_t)(oco * NN + y) * NN) * 2;
                *(float2*)&out[base + px0 * 2] = make_float2(v0, v1);
                *(float2*)&out[base + px1 * 2] = make_float2(v2, v3);
            }
        }
    }
}

// ---------------- launcher ----------------
extern "C" void kernel_launch(void* const* d_in, const int* in_sizes, int n_in,
                              void* d_out, int out_size) {
    const float* x0   = (const float*)d_in[0];
    const float* x1   = (const float*)d_in[1];
    const float* fil0 = (const float*)d_in[2];
    const float* fil1 = (const float*)d_in[3];
    const float* fil2 = (const float*)d_in[4];
    const float* w00  = (const float*)d_in[5];
    const float* w01  = (const float*)d_in[6];
    const float* w10  = (const float*)d_in[7];
    const float* w11  = (const float*)d_in[8];
    const float* b0   = (const float*)d_in[9];
    const float* b1   = (const float*)d_in[10];
    float* out = (float*)d_out;

    k_weights<<<(COUT * CIN + 255) / 256, 256>>>(fil0, fil1, fil2, w00, w01, w10, w11);
    k_xpack<<<dim3(512, 3), 128>>>(x0, x1);
    k_meanred<<<CIN, 128>>>();
    k_addconst<<<COUT, 256>>>(b0, b1);

    const int dyn_smem = 3 * STG;  // 172032
    cudaFuncSetAttribute(k_conv, cudaFuncAttributeMaxDynamicSharedMemorySize, dyn_smem);
    k_conv<<<256, 512, dyn_smem>>>(out);
}

// round 9
// speedup vs baseline: 1.1865x; 1.1865x over previous
#include <cuda_runtime.h>
#include <cuda_fp16.h>
#include <cstdint>

#define NN     256
#define NPIX   65536
#define CIN    192
#define COUT   192
#define NCHUNK 27
#define STG    40960          // stage: A 16K | B 24K

// ---------------- device scratch ----------------
__device__ float g_Wsum[COUT * CIN];     // per-(OC,IC) sum over taps
__device__ float g_meanin[CIN];
__device__ float g_add[COUT];
__device__ float g_psum[3 * 64 * 512];   // per-block channel partial sums
__device__ __align__(1024) __half g_Wh[(size_t)NCHUNK * 12288];  // [chunk] 192x64 fp16 swizzled
__device__ __align__(16) uint32_t g_xh[(size_t)3 * NPIX * 32];   // [c][pix][k2] fp16 pairs

// ---------------- helpers ----------------
__device__ __forceinline__ uint32_t smem_u32(const void* p) {
    uint32_t a;
    asm("{ .reg .u64 t; cvta.to.shared.u64 t, %1; cvt.u32.u64 %0, t; }" : "=r"(a) : "l"(p));
    return a;
}
__device__ __forceinline__ uint32_t swz(uint32_t off) { return off ^ ((off >> 3) & 0x70); }
__device__ __forceinline__ void ldsm4(uint32_t* r, uint32_t addr) {
    asm volatile("ldmatrix.sync.aligned.m8n8.x4.shared.b16 {%0,%1,%2,%3}, [%4];"
                 : "=r"(r[0]), "=r"(r[1]), "=r"(r[2]), "=r"(r[3]) : "r"(addr));
}
__device__ __forceinline__ void mma16816(float* d, const uint32_t* a, const uint32_t* b) {
    asm volatile("mma.sync.aligned.m16n8k16.row.col.f32.f16.f16.f32 "
                 "{%0,%1,%2,%3}, {%4,%5,%6,%7}, {%8,%9}, {%0,%1,%2,%3};"
                 : "+f"(d[0]), "+f"(d[1]), "+f"(d[2]), "+f"(d[3])
                 : "r"(a[0]), "r"(a[1]), "r"(a[2]), "r"(a[3]), "r"(b[0]), "r"(b[1]));
}
__device__ __forceinline__ void cpa16(uint32_t dst, const void* src) {
    asm volatile("cp.async.cg.shared.global [%0], [%1], 16;" :: "r"(dst), "l"(src));
}

// ================= launch 0: weight synthesis -> fp16 tiles + tap-sums =================
__global__ void k_weights(const float* __restrict__ fil0, const float* __restrict__ fil1,
                          const float* __restrict__ fil2, const float* __restrict__ w00,
                          const float* __restrict__ w01, const float* __restrict__ w10,
                          const float* __restrict__ w11) {
    int idx = blockIdx.x * blockDim.x + threadIdx.x;
    if (idx >= COUT * CIN) return;
    int OC = idx / CIN, IC = idx % CIN;
    float acc[9];
#pragma unroll
    for (int t = 0; t < 9; t++) acc[t] = 0.f;
    if (OC < 64) {
        if (IC < 64) {
            for (int k = 0; k < 3; k++) {
                float c = w00[(OC * 64 + IC) * 3 + k];
#pragma unroll
                for (int t = 0; t < 9; t++) acc[t] += c * fil0[k * 9 + t];
            }
        } else {
            int ici = (IC - 64) >> 1, tin = (IC - 64) & 1;
            for (int k = 0; k < 6; k++) {
                float c = w10[(OC * 64 + ici) * 6 + k];
#pragma unroll
                for (int t = 0; t < 9; t++) acc[t] += c * fil1[(k * 9 + t) * 2 + tin];
            }
        }
    } else {
        int oco = (OC - 64) >> 1, tout = (OC - 64) & 1;
        if (IC < 64) {
            for (int k = 0; k < 6; k++) {
                float c = w01[(oco * 64 + IC) * 6 + k];
#pragma unroll
                for (int t = 0; t < 9; t++) acc[t] += c * fil1[(k * 9 + t) * 2 + tout];
            }
        } else {
            int ici = (IC - 64) >> 1, tin = (IC - 64) & 1;
            for (int k = 0; k < 12; k++) {
                float c = w11[(oco * 64 + ici) * 12 + k];
#pragma unroll
                for (int t = 0; t < 9; t++) acc[t] += c * fil2[((k * 9 + t) * 2 + tin) * 2 + tout];
            }
        }
    }
    float s = 0.f;
    int cg = IC >> 6, kk = IC & 63;
    uint32_t sw = swz((uint32_t)(OC * 128 + kk * 2)) >> 1;
#pragma unroll
    for (int t = 0; t < 9; t++) {
        s += acc[t];
        g_Wh[(size_t)(t * 3 + cg) * 12288 + sw] = __float2half_rn(acc[t]);
    }
    g_Wsum[idx] = s;
}

// ================= launch 1: x -> pixel-major fp16 planes + partial channel sums =================
#define XS 36   // smem row stride in words (144 B)
__global__ void k_xpack(const float* __restrict__ x0, const float* __restrict__ x1) {
    __shared__ uint32_t shh[128 * XS];
    __shared__ float red[64][2];
    const int c = blockIdx.y, tid = threadIdx.x;
    const int px = blockIdx.x * 128 + tid;
#pragma unroll 4
    for (int k2 = 0; k2 < 32; k2++) {
        float v0, v1;
        if (c == 0) {
            v0 = x0[(size_t)(2 * k2) * NPIX + px];
            v1 = x0[(size_t)(2 * k2 + 1) * NPIX + px];
        } else {
            int j = (c - 1) * 64 + 2 * k2;
            float2 p = *(const float2*)&x1[((size_t)(j >> 1) * NPIX + px) * 2];
            v0 = p.x; v1 = p.y;
        }
        __half h0 = __float2half_rn(v0), h1 = __float2half_rn(v1);
        shh[tid * XS + k2] = (uint32_t)__half_as_ushort(h0) | ((uint32_t)__half_as_ushort(h1) << 16);
    }
    __syncthreads();
#pragma unroll
    for (int r = 0; r < 8; r++) {
        int s = tid + 128 * r;
        int pl = s >> 3, q = s & 7;
        uint4 vh = *(const uint4*)&shh[pl * XS + q * 4];
        size_t o = ((size_t)c * NPIX + blockIdx.x * 128 + pl) * 32 + q * 4;
        *(uint4*)&g_xh[o] = vh;
    }
    {
        int ch = tid & 63, seg = tid >> 6;
        int k2 = ch >> 1, half = ch & 1;
        float s = 0.f;
        for (int p = 0; p < 64; p++) {
            uint32_t w = shh[(seg * 64 + p) * XS + k2];
            s += __half2float(__ushort_as_half((unsigned short)(half ? (w >> 16) : (w & 0xFFFF))));
        }
        red[ch][seg] = s;
        __syncthreads();
        if (tid < 64)
            g_psum[(c * 64 + tid) * 512 + blockIdx.x] = red[tid][0] + red[tid][1];
    }
}

// ================= launch 2: reduce channel means =================
__global__ void k_meanred() {
    __shared__ float sm[128];
    int ch = blockIdx.x;
    float s = 0.f;
    for (int i = threadIdx.x; i < 512; i += 128) s += g_psum[ch * 512 + i];
    sm[threadIdx.x] = s;
    __syncthreads();
    for (int o = 64; o > 0; o >>= 1) {
        if (threadIdx.x < o) sm[threadIdx.x] += sm[threadIdx.x + o];
        __syncthreads();
    }
    if (threadIdx.x == 0) g_meanin[ch] = sm[0] * (1.f / NPIX);
}

// ================= launch 3: per-OC additive const =================
__global__ void k_addconst(const float* __restrict__ b0, const float* __restrict__ b1) {
    __shared__ float sm[256];
    int OC = blockIdx.x, tid = threadIdx.x;
    float s = 0.f;
    if (tid < CIN) s = g_Wsum[OC * CIN + tid] * g_meanin[tid];
    sm[tid] = s;
    __syncthreads();
    for (int o = 128; o > 0; o >>= 1) {
        if (tid < o) sm[tid] += sm[tid + o];
        __syncthreads();
    }
    if (tid == 0) g_add[OC] = (OC < 64) ? b0[OC] : sm[0] * b1[(OC - 64) >> 1];
}

// ================= launch 4: conv = implicit GEMM, 4Mx4N warps, frag double-buffer =================
// 512 CTAs (128 px each), 512 thr = 16 warps (4M x 4N), warp tile m32 x n48, 3 stages.
__global__ __launch_bounds__(512) void k_conv(float* __restrict__ out) {
    extern __shared__ __align__(1024) char smem[];
    const uint32_t sb = smem_u32(smem);
    const int tid = threadIdx.x;
    const int lane = tid & 31, warp = tid >> 5;
    const int wm = warp & 3, wn = warp >> 2;
    const int y = blockIdx.x >> 1, xb = (blockIdx.x & 1) << 7;

    const int a_row = (lane & 7) + ((lane >> 3) & 1) * 8;
    const int a_ks  = lane >> 4;
    const int b_row = (lane & 7) + ((lane >> 4) << 3);
    const int b_ks  = (lane >> 3) & 1;

    const int am = tid >> 2;         // A row loaded by this thread (0..127)
    const int aq = (tid & 3) * 2;    // first 16B chunk (0,2,4,6)

    float acc[2][6][4];
#pragma unroll
    for (int t = 0; t < 2; t++)
#pragma unroll
        for (int g = 0; g < 6; g++)
#pragma unroll
            for (int q = 0; q < 4; q++) acc[t][g][q] = 0.f;

#define ISSUE(I, S)                                                                  \
    {                                                                                \
        int tap = (I) / 3, c = (I) % 3;                                              \
        int ky = tap / 3, kx = tap % 3;                                              \
        int gy = (y + ky + 255) & 255;                                               \
        int gx = (xb + am + kx + 255) & 255;                                         \
        size_t so = ((size_t)((c << 16) + (gy << 8) + gx)) * 128 + (size_t)(aq * 16);\
        _Pragma("unroll")                                                            \
        for (int j = 0; j < 2; j++) {                                                \
            uint32_t d = sb + (S) * STG + swz((uint32_t)(am * 128 + (aq + j) * 16)); \
            cpa16(d, (const char*)g_xh + so + j * 16);                               \
        }                                                                            \
        const char* bs = (const char*)g_Wh + (size_t)(I) * 24576;                    \
        _Pragma("unroll")                                                            \
        for (int j = 0; j < 3; j++) {                                                \
            int off = (tid + 512 * j) * 16;                                          \
            cpa16(sb + (S) * STG + 16384 + off, bs + off);                           \
        }                                                                            \
        asm volatile("cp.async.commit_group;");                                      \
    }

#define LOADFRAG(KS, B)                                                              \
    {                                                                                \
        _Pragma("unroll")                                                            \
        for (int t = 0; t < 2; t++)                                                  \
            ldsm4(ah[B][t], Ab + swz((uint32_t)((wm * 32 + t * 16 + a_row) * 128 + (KS) * 32 + a_ks * 16))); \
        _Pragma("unroll")                                                            \
        for (int g = 0; g < 3; g++)                                                  \
            ldsm4(bh[B][g], Bb + swz((uint32_t)((wn * 48 + g * 16 + b_row) * 128 + (KS) * 32 + b_ks * 16))); \
    }

    ISSUE(0, 0);
    ISSUE(1, 1);

#pragma unroll 3
    for (int i = 0; i < NCHUNK; i++) {
        if (i < NCHUNK - 2) { asm volatile("cp.async.wait_group 1;" ::: "memory"); }
        else                { asm volatile("cp.async.wait_group 0;" ::: "memory"); }
        __syncthreads();
        if (i + 2 < NCHUNK) ISSUE(i + 2, (i + 2) % 3);

        const uint32_t Ab = sb + (i % 3) * STG;
        const uint32_t Bb = Ab + 16384;

        uint32_t ah[2][2][4], bh[2][3][4];
        LOADFRAG(0, 0);
#pragma unroll
        for (int ks = 0; ks < 4; ks++) {
            const int cur = ks & 1;
            if (ks < 3) LOADFRAG(ks + 1, cur ^ 1);
#pragma unroll
            for (int g = 0; g < 3; g++)
#pragma unroll
                for (int t = 0; t < 2; t++)
#pragma unroll
                    for (int h = 0; h < 2; h++)
                        mma16816(acc[t][g * 2 + h], ah[cur][t], bh[cur][g] + 2 * h);
        }
    }
#undef ISSUE
#undef LOADFRAG

    // ---- epilogue ----
    const int col = (lane & 3) * 2;
    const int rowq = lane >> 2;
#pragma unroll
    for (int t = 0; t < 2; t++) {
        int px0 = xb + wm * 32 + t * 16 + rowq;
        int px1 = px0 + 8;
#pragma unroll
        for (int nf = 0; nf < 6; nf++) {
            int n = wn * 48 + nf * 8 + col;
            float g0 = __ldg(&g_add[n]), g1 = __ldg(&g_add[n + 1]);
            float v0 = acc[t][nf][0] + g0, v1 = acc[t][nf][1] + g1;
            float v2 = acc[t][nf][2] + g0, v3 = acc[t][nf][3] + g1;
            if (n < 64) {
                out[(size_t)n * NPIX + y * NN + px0]       = v0;
                out[(size_t)(n + 1) * NPIX + y * NN + px0] = v1;
                out[(size_t)n * NPIX + y * NN + px1]       = v2;
                out[(size_t)(n + 1) * NPIX + y * NN + px1] = v3;
            } else {
                int oco = (n - 64) >> 1;
                size_t base = (size_t)64 * NPIX + ((size_t)(oco * NN + y) * NN) * 2;
                *(float2*)&out[base + px0 * 2] = make_float2(v0, v1);
                *(float2*)&out[base + px1 * 2] = make_float2(v2, v3);
            }
        }
    }
}

// ---------------- launcher ----------------
extern "C" void kernel_launch(void* const* d_in, const int* in_sizes, int n_in,
                              void* d_out, int out_size) {
    const float* x0   = (const float*)d_in[0];
    const float* x1   = (const float*)d_in[1];
    const float* fil0 = (const float*)d_in[2];
    const float* fil1 = (const float*)d_in[3];
    const float* fil2 = (const float*)d_in[4];
    const float* w00  = (const float*)d_in[5];
    const float* w01  = (const float*)d_in[6];
    const float* w10  = (const float*)d_in[7];
    const float* w11  = (const float*)d_in[8];
    const float* b0   = (const float*)d_in[9];
    const float* b1   = (const float*)d_in[10];
    float* out = (float*)d_out;

    k_weights<<<(COUT * CIN + 255) / 256, 256>>>(fil0, fil1, fil2, w00, w01, w10, w11);
    k_xpack<<<dim3(512, 3), 128>>>(x0, x1);
    k_meanred<<<CIN, 128>>>();
    k_addconst<<<COUT, 256>>>(b0, b1);

    const int dyn_smem = 3 * STG;  // 122880
    cudaFuncSetAttribute(k_conv, cudaFuncAttributeMaxDynamicSharedMemorySize, dyn_smem);
    k_conv<<<512, 512, dyn_smem>>>(out);
}

// round 10
// speedup vs baseline: 1.2373x; 1.0428x over previous
#include <cuda_runtime.h>
#include <cuda_fp16.h>
#include <cstdint>

#define NN     256
#define NPIX   65536
#define CIN    192
#define COUT   192
#define NCHUNK 27
#define STG    28672          // stage: A 16K | B 12K

// ---------------- device scratch ----------------
__device__ float g_Wsum[COUT * CIN];     // per-(OC,IC) sum over taps
__device__ float g_meanin[CIN];
__device__ float g_add[COUT];
__device__ float g_psum[3 * 64 * 512];   // per-block channel partial sums
__device__ __align__(1024) __half g_Wh[(size_t)NCHUNK * 12288];  // [chunk] 192x64 fp16 swizzled
__device__ __align__(16) uint32_t g_xh[(size_t)3 * NPIX * 32];   // [c][pix][k2] fp16 pairs

// ---------------- helpers ----------------
__device__ __forceinline__ uint32_t smem_u32(const void* p) {
    uint32_t a;
    asm("{ .reg .u64 t; cvta.to.shared.u64 t, %1; cvt.u32.u64 %0, t; }" : "=r"(a) : "l"(p));
    return a;
}
__device__ __forceinline__ uint32_t swz(uint32_t off) { return off ^ ((off >> 3) & 0x70); }
__device__ __forceinline__ void ldsm4(uint32_t* r, uint32_t addr) {
    asm volatile("ldmatrix.sync.aligned.m8n8.x4.shared.b16 {%0,%1,%2,%3}, [%4];"
                 : "=r"(r[0]), "=r"(r[1]), "=r"(r[2]), "=r"(r[3]) : "r"(addr));
}
__device__ __forceinline__ void mma16816(float* d, const uint32_t* a, const uint32_t* b) {
    asm volatile("mma.sync.aligned.m16n8k16.row.col.f32.f16.f16.f32 "
                 "{%0,%1,%2,%3}, {%4,%5,%6,%7}, {%8,%9}, {%0,%1,%2,%3};"
                 : "+f"(d[0]), "+f"(d[1]), "+f"(d[2]), "+f"(d[3])
                 : "r"(a[0]), "r"(a[1]), "r"(a[2]), "r"(a[3]), "r"(b[0]), "r"(b[1]));
}
__device__ __forceinline__ void cpa16(uint32_t dst, const void* src) {
    asm volatile("cp.async.cg.shared.global [%0], [%1], 16;" :: "r"(dst), "l"(src));
}

// ================= launch 0: weight synthesis -> fp16 tiles + tap-sums =================
__global__ void k_weights(const float* __restrict__ fil0, const float* __restrict__ fil1,
                          const float* __restrict__ fil2, const float* __restrict__ w00,
                          const float* __restrict__ w01, const float* __restrict__ w10,
                          const float* __restrict__ w11) {
    int idx = blockIdx.x * blockDim.x + threadIdx.x;
    if (idx >= COUT * CIN) return;
    int OC = idx / CIN, IC = idx % CIN;
    float acc[9];
#pragma unroll
    for (int t = 0; t < 9; t++) acc[t] = 0.f;
    if (OC < 64) {
        if (IC < 64) {
            for (int k = 0; k < 3; k++) {
                float c = w00[(OC * 64 + IC) * 3 + k];
#pragma unroll
                for (int t = 0; t < 9; t++) acc[t] += c * fil0[k * 9 + t];
            }
        } else {
            int ici = (IC - 64) >> 1, tin = (IC - 64) & 1;
            for (int k = 0; k < 6; k++) {
                float c = w10[(OC * 64 + ici) * 6 + k];
#pragma unroll
                for (int t = 0; t < 9; t++) acc[t] += c * fil1[(k * 9 + t) * 2 + tin];
            }
        }
    } else {
        int oco = (OC - 64) >> 1, tout = (OC - 64) & 1;
        if (IC < 64) {
            for (int k = 0; k < 6; k++) {
                float c = w01[(oco * 64 + IC) * 6 + k];
#pragma unroll
                for (int t = 0; t < 9; t++) acc[t] += c * fil1[(k * 9 + t) * 2 + tout];
            }
        } else {
            int ici = (IC - 64) >> 1, tin = (IC - 64) & 1;
            for (int k = 0; k < 12; k++) {
                float c = w11[(oco * 64 + ici) * 12 + k];
#pragma unroll
                for (int t = 0; t < 9; t++) acc[t] += c * fil2[((k * 9 + t) * 2 + tin) * 2 + tout];
            }
        }
    }
    float s = 0.f;
    int cg = IC >> 6, kk = IC & 63;
    uint32_t sw = swz((uint32_t)(OC * 128 + kk * 2)) >> 1;
#pragma unroll
    for (int t = 0; t < 9; t++) {
        s += acc[t];
        g_Wh[(size_t)(t * 3 + cg) * 12288 + sw] = __float2half_rn(acc[t]);
    }
    g_Wsum[idx] = s;
}

// ================= launch 1: x -> pixel-major fp16 planes + partial channel sums =================
#define XS 36   // smem row stride in words (144 B)
__global__ void k_xpack(const float* __restrict__ x0, const float* __restrict__ x1) {
    __shared__ uint32_t shh[128 * XS];
    __shared__ float red[64][2];
    const int c = blockIdx.y, tid = threadIdx.x;
    const int px = blockIdx.x * 128 + tid;
#pragma unroll 4
    for (int k2 = 0; k2 < 32; k2++) {
        float v0, v1;
        if (c == 0) {
            v0 = x0[(size_t)(2 * k2) * NPIX + px];
            v1 = x0[(size_t)(2 * k2 + 1) * NPIX + px];
        } else {
            int j = (c - 1) * 64 + 2 * k2;
            float2 p = *(const float2*)&x1[((size_t)(j >> 1) * NPIX + px) * 2];
            v0 = p.x; v1 = p.y;
        }
        __half h0 = __float2half_rn(v0), h1 = __float2half_rn(v1);
        shh[tid * XS + k2] = (uint32_t)__half_as_ushort(h0) | ((uint32_t)__half_as_ushort(h1) << 16);
    }
    __syncthreads();
#pragma unroll
    for (int r = 0; r < 8; r++) {
        int s = tid + 128 * r;
        int pl = s >> 3, q = s & 7;
        uint4 vh = *(const uint4*)&shh[pl * XS + q * 4];
        size_t o = ((size_t)c * NPIX + blockIdx.x * 128 + pl) * 32 + q * 4;
        *(uint4*)&g_xh[o] = vh;
    }
    {
        int ch = tid & 63, seg = tid >> 6;
        int k2 = ch >> 1, half = ch & 1;
        float s = 0.f;
        for (int p = 0; p < 64; p++) {
            uint32_t w = shh[(seg * 64 + p) * XS + k2];
            s += __half2float(__ushort_as_half((unsigned short)(half ? (w >> 16) : (w & 0xFFFF))));
        }
        red[ch][seg] = s;
        __syncthreads();
        if (tid < 64)
            g_psum[(c * 64 + tid) * 512 + blockIdx.x] = red[tid][0] + red[tid][1];
    }
}

// ================= launch 2: reduce channel means =================
__global__ void k_meanred() {
    __shared__ float sm[128];
    int ch = blockIdx.x;
    float s = 0.f;
    for (int i = threadIdx.x; i < 512; i += 128) s += g_psum[ch * 512 + i];
    sm[threadIdx.x] = s;
    __syncthreads();
    for (int o = 64; o > 0; o >>= 1) {
        if (threadIdx.x < o) sm[threadIdx.x] += sm[threadIdx.x + o];
        __syncthreads();
    }
    if (threadIdx.x == 0) g_meanin[ch] = sm[0] * (1.f / NPIX);
}

// ================= launch 3: per-OC additive const =================
__global__ void k_addconst(const float* __restrict__ b0, const float* __restrict__ b1) {
    __shared__ float sm[256];
    int OC = blockIdx.x, tid = threadIdx.x;
    float s = 0.f;
    if (tid < CIN) s = g_Wsum[OC * CIN + tid] * g_meanin[tid];
    sm[tid] = s;
    __syncthreads();
    for (int o = 128; o > 0; o >>= 1) {
        if (tid < o) sm[tid] += sm[tid + o];
        __syncthreads();
    }
    if (tid == 0) g_add[OC] = (OC < 64) ? b0[OC] : sm[0] * b1[(OC - 64) >> 1];
}

// ================= launch 4: conv = implicit GEMM, M=128 N=96 per CTA, 2 CTAs/SM =================
// 1024 CTAs (512 px-tiles x 2 n-halves), 256 thr = 8 warps (4M x 2N), warp tile m32 x n48.
// 3 stages x 28KB, fragment double-buffer across ks.
__global__ __launch_bounds__(256, 2) void k_conv(float* __restrict__ out) {
    extern __shared__ __align__(1024) char smem[];
    const uint32_t sb = smem_u32(smem);
    const int tid = threadIdx.x;
    const int lane = tid & 31, warp = tid >> 5;
    const int wm = warp & 3, wn = warp >> 2;
    const int nh = blockIdx.x & 1;
    const int tile = blockIdx.x >> 1;
    const int y = tile >> 1, xb = (tile & 1) << 7;

    const int a_row = (lane & 7) + ((lane >> 3) & 1) * 8;
    const int a_ks  = lane >> 4;
    const int b_row = (lane & 7) + ((lane >> 4) << 3);
    const int b_ks  = (lane >> 3) & 1;

    const int am = tid >> 1;         // A row loaded by this thread (0..127)
    const int aq = (tid & 1) * 4;    // first 16B chunk (0 or 4)

    float acc[2][6][4];
#pragma unroll
    for (int t = 0; t < 2; t++)
#pragma unroll
        for (int g = 0; g < 6; g++)
#pragma unroll
            for (int q = 0; q < 4; q++) acc[t][g][q] = 0.f;

#define ISSUE(I, S)                                                                  \
    {                                                                                \
        int tap = (I) / 3, c = (I) % 3;                                              \
        int ky = tap / 3, kx = tap % 3;                                              \
        int gy = (y + ky + 255) & 255;                                               \
        int gx = (xb + am + kx + 255) & 255;                                         \
        size_t so = ((size_t)((c << 16) + (gy << 8) + gx)) * 128 + (size_t)(aq * 16);\
        _Pragma("unroll")                                                            \
        for (int j = 0; j < 4; j++) {                                                \
            uint32_t d = sb + (S) * STG + swz((uint32_t)(am * 128 + (aq + j) * 16)); \
            cpa16(d, (const char*)g_xh + so + j * 16);                               \
        }                                                                            \
        const char* bs = (const char*)g_Wh + (size_t)(I) * 24576 + nh * 12288;       \
        _Pragma("unroll")                                                            \
        for (int j = 0; j < 3; j++) {                                                \
            int off = (tid + 256 * j) * 16;                                          \
            cpa16(sb + (S) * STG + 16384 + off, bs + off);                           \
        }                                                                            \
        asm volatile("cp.async.commit_group;");                                      \
    }

#define LOADFRAG(KS, B)                                                              \
    {                                                                                \
        _Pragma("unroll")                                                            \
        for (int t = 0; t < 2; t++)                                                  \
            ldsm4(ah[B][t], Ab + swz((uint32_t)((wm * 32 + t * 16 + a_row) * 128 + (KS) * 32 + a_ks * 16))); \
        _Pragma("unroll")                                                            \
        for (int g = 0; g < 3; g++)                                                  \
            ldsm4(bh[B][g], Bb + swz((uint32_t)((wn * 48 + g * 16 + b_row) * 128 + (KS) * 32 + b_ks * 16))); \
    }

    ISSUE(0, 0);
    ISSUE(1, 1);

#pragma unroll 3
    for (int i = 0; i < NCHUNK; i++) {
        if (i < NCHUNK - 2) { asm volatile("cp.async.wait_group 1;" ::: "memory"); }
        else                { asm volatile("cp.async.wait_group 0;" ::: "memory"); }
        __syncthreads();
        if (i + 2 < NCHUNK) ISSUE(i + 2, (i + 2) % 3);

        const uint32_t Ab = sb + (i % 3) * STG;
        const uint32_t Bb = Ab + 16384;

        uint32_t ah[2][2][4], bh[2][3][4];
        LOADFRAG(0, 0);
#pragma unroll
        for (int ks = 0; ks < 4; ks++) {
            const int cur = ks & 1;
            if (ks < 3) LOADFRAG(ks + 1, cur ^ 1);
#pragma unroll
            for (int g = 0; g < 3; g++)
#pragma unroll
                for (int t = 0; t < 2; t++)
#pragma unroll
                    for (int h = 0; h < 2; h++)
                        mma16816(acc[t][g * 2 + h], ah[cur][t], bh[cur][g] + 2 * h);
        }
    }
#undef ISSUE
#undef LOADFRAG

    // ---- epilogue ----
    const int col = (lane & 3) * 2;
    const int rowq = lane >> 2;
#pragma unroll
    for (int t = 0; t < 2; t++) {
        int px0 = xb + wm * 32 + t * 16 + rowq;
        int px1 = px0 + 8;
#pragma unroll
        for (int nf = 0; nf < 6; nf++) {
            int n = nh * 96 + wn * 48 + nf * 8 + col;
            float g0 = __ldg(&g_add[n]), g1 = __ldg(&g_add[n + 1]);
            float v0 = acc[t][nf][0] + g0, v1 = acc[t][nf][1] + g1;
            float v2 = acc[t][nf][2] + g0, v3 = acc[t][nf][3] + g1;
            if (n < 64) {
                out[(size_t)n * NPIX + y * NN + px0]       = v0;
                out[(size_t)(n + 1) * NPIX + y * NN + px0] = v1;
                out[(size_t)n * NPIX + y * NN + px1]       = v2;
                out[(size_t)(n + 1) * NPIX + y * NN + px1] = v3;
            } else {
                int oco = (n - 64) >> 1;
                size_t base = (size_t)64 * NPIX + ((size_t)(oco * NN + y) * NN) * 2;
                *(float2*)&out[base + px0 * 2] = make_float2(v0, v1);
                *(float2*)&out[base + px1 * 2] = make_float2(v2, v3);
            }
        }
    }
}

// ---------------- launcher ----------------
extern "C" void kernel_launch(void* const* d_in, const int* in_sizes, int n_in,
                              void* d_out, int out_size) {
    const float* x0   = (const float*)d_in[0];
    const float* x1   = (const float*)d_in[1];
    const float* fil0 = (const float*)d_in[2];
    const float* fil1 = (const float*)d_in[3];
    const float* fil2 = (const float*)d_in[4];
    const float* w00  = (const float*)d_in[5];
    const float* w01  = (const float*)d_in[6];
    const float* w10  = (const float*)d_in[7];
    const float* w11  = (const float*)d_in[8];
    const float* b0   = (const float*)d_in[9];
    const float* b1   = (const float*)d_in[10];
    float* out = (float*)d_out;

    k_weights<<<(COUT * CIN + 255) / 256, 256>>>(fil0, fil1, fil2, w00, w01, w10, w11);
    k_xpack<<<dim3(512, 3), 128>>>(x0, x1);
    k_meanred<<<CIN, 128>>>();
    k_addconst<<<COUT, 256>>>(b0, b1);

    const int dyn_smem = 3 * STG;  // 86016
    cudaFuncSetAttribute(k_conv, cudaFuncAttributeMaxDynamicSharedMemorySize, dyn_smem);
    k_conv<<<1024, 256, dyn_smem>>>(out);
}

// round 11
// speedup vs baseline: 1.3029x; 1.0530x over previous
#include <cuda_runtime.h>
#include <cuda_fp16.h>
#include <cstdint>

#define NN     256
#define NPIX   65536
#define CIN    192
#define COUT   192
#define NCHUNK 27
#define STG    28672          // stage: A 16K | B 12K

// ---------------- device scratch ----------------
__device__ float g_Wsum[COUT * CIN];     // per-(OC,IC) sum over taps
__device__ float g_meanin[CIN];
__device__ float g_add[COUT];
__device__ float g_psum[3 * 64 * 512];   // per-block channel partial sums
__device__ __align__(1024) __half g_Wh[(size_t)NCHUNK * 12288];  // [chunk] 192x64 fp16 swizzled
__device__ __align__(16) uint32_t g_xh[(size_t)3 * NPIX * 32];   // [c][pix][k2] fp16 pairs

// ---------------- helpers ----------------
__device__ __forceinline__ uint32_t smem_u32(const void* p) {
    uint32_t a;
    asm("{ .reg .u64 t; cvta.to.shared.u64 t, %1; cvt.u32.u64 %0, t; }" : "=r"(a) : "l"(p));
    return a;
}
__device__ __forceinline__ uint32_t swz(uint32_t off) { return off ^ ((off >> 3) & 0x70); }
__device__ __forceinline__ void ldsm4(uint32_t* r, uint32_t addr) {
    asm volatile("ldmatrix.sync.aligned.m8n8.x4.shared.b16 {%0,%1,%2,%3}, [%4];"
                 : "=r"(r[0]), "=r"(r[1]), "=r"(r[2]), "=r"(r[3]) : "r"(addr));
}
__device__ __forceinline__ void mma16816(float* d, const uint32_t* a, const uint32_t* b) {
    asm volatile("mma.sync.aligned.m16n8k16.row.col.f32.f16.f16.f32 "
                 "{%0,%1,%2,%3}, {%4,%5,%6,%7}, {%8,%9}, {%0,%1,%2,%3};"
                 : "+f"(d[0]), "+f"(d[1]), "+f"(d[2]), "+f"(d[3])
                 : "r"(a[0]), "r"(a[1]), "r"(a[2]), "r"(a[3]), "r"(b[0]), "r"(b[1]));
}
__device__ __forceinline__ void cpa16(uint32_t dst, const void* src) {
    asm volatile("cp.async.cg.shared.global [%0], [%1], 16;" :: "r"(dst), "l"(src));
}

// ---------------- weight synthesis body (one (OC,IC) pair per thread) ----------------
__device__ __forceinline__ void weights_body(int idx,
        const float* __restrict__ fil0, const float* __restrict__ fil1,
        const float* __restrict__ fil2, const float* __restrict__ w00,
        const float* __restrict__ w01, const float* __restrict__ w10,
        const float* __restrict__ w11) {
    int OC = idx / CIN, IC = idx % CIN;
    float acc[9];
#pragma unroll
    for (int t = 0; t < 9; t++) acc[t] = 0.f;
    if (OC < 64) {
        if (IC < 64) {
            for (int k = 0; k < 3; k++) {
                float c = w00[(OC * 64 + IC) * 3 + k];
#pragma unroll
                for (int t = 0; t < 9; t++) acc[t] += c * fil0[k * 9 + t];
            }
        } else {
            int ici = (IC - 64) >> 1, tin = (IC - 64) & 1;
            for (int k = 0; k < 6; k++) {
                float c = w10[(OC * 64 + ici) * 6 + k];
#pragma unroll
                for (int t = 0; t < 9; t++) acc[t] += c * fil1[(k * 9 + t) * 2 + tin];
            }
        }
    } else {
        int oco = (OC - 64) >> 1, tout = (OC - 64) & 1;
        if (IC < 64) {
            for (int k = 0; k < 6; k++) {
                float c = w01[(oco * 64 + IC) * 6 + k];
#pragma unroll
                for (int t = 0; t < 9; t++) acc[t] += c * fil1[(k * 9 + t) * 2 + tout];
            }
        } else {
            int ici = (IC - 64) >> 1, tin = (IC - 64) & 1;
            for (int k = 0; k < 12; k++) {
                float c = w11[(oco * 64 + ici) * 12 + k];
#pragma unroll
                for (int t = 0; t < 9; t++) acc[t] += c * fil2[((k * 9 + t) * 2 + tin) * 2 + tout];
            }
        }
    }
    float s = 0.f;
    int cg = IC >> 6, kk = IC & 63;
    uint32_t sw = swz((uint32_t)(OC * 128 + kk * 2)) >> 1;
#pragma unroll
    for (int t = 0; t < 9; t++) {
        s += acc[t];
        g_Wh[(size_t)(t * 3 + cg) * 12288 + sw] = __float2half_rn(acc[t]);
    }
    g_Wsum[idx] = s;
}

// ================= launch 0: x pack + weight synthesis (fused roles) =================
// grid (512, 4) block 128. y<3: pack role (c=y, 128 pixels). y==3: weights role.
#define XS 36   // smem row stride in words (144 B)
__global__ void k_xpack(const float* __restrict__ x0, const float* __restrict__ x1,
                        const float* __restrict__ fil0, const float* __restrict__ fil1,
                        const float* __restrict__ fil2, const float* __restrict__ w00,
                        const float* __restrict__ w01, const float* __restrict__ w10,
                        const float* __restrict__ w11) {
    if (blockIdx.y == 3) {
        int idx = blockIdx.x * 128 + threadIdx.x;
        if (idx < COUT * CIN) weights_body(idx, fil0, fil1, fil2, w00, w01, w10, w11);
        return;
    }
    __shared__ uint32_t shh[128 * XS];
    __shared__ float red[64][2];
    const int c = blockIdx.y, tid = threadIdx.x;
    const int px = blockIdx.x * 128 + tid;
#pragma unroll 8
    for (int k2 = 0; k2 < 32; k2++) {
        float v0, v1;
        if (c == 0) {
            v0 = x0[(size_t)(2 * k2) * NPIX + px];
            v1 = x0[(size_t)(2 * k2 + 1) * NPIX + px];
        } else {
            int j = (c - 1) * 64 + 2 * k2;
            float2 p = *(const float2*)&x1[((size_t)(j >> 1) * NPIX + px) * 2];
            v0 = p.x; v1 = p.y;
        }
        __half h0 = __float2half_rn(v0), h1 = __float2half_rn(v1);
        shh[tid * XS + k2] = (uint32_t)__half_as_ushort(h0) | ((uint32_t)__half_as_ushort(h1) << 16);
    }
    __syncthreads();
#pragma unroll
    for (int r = 0; r < 8; r++) {
        int s = tid + 128 * r;
        int pl = s >> 3, q = s & 7;
        uint4 vh = *(const uint4*)&shh[pl * XS + q * 4];
        size_t o = ((size_t)c * NPIX + blockIdx.x * 128 + pl) * 32 + q * 4;
        *(uint4*)&g_xh[o] = vh;
    }
    {
        int ch = tid & 63, seg = tid >> 6;
        int k2 = ch >> 1, half = ch & 1;
        float s = 0.f;
        for (int p = 0; p < 64; p++) {
            uint32_t w = shh[(seg * 64 + p) * XS + k2];
            s += __half2float(__ushort_as_half((unsigned short)(half ? (w >> 16) : (w & 0xFFFF))));
        }
        red[ch][seg] = s;
        __syncthreads();
        if (tid < 64)
            g_psum[(c * 64 + tid) * 512 + blockIdx.x] = red[tid][0] + red[tid][1];
    }
}

// ================= launch 1: reduce channel means =================
__global__ void k_meanred() {
    __shared__ float sm[128];
    int ch = blockIdx.x;
    float s = 0.f;
    for (int i = threadIdx.x; i < 512; i += 128) s += g_psum[ch * 512 + i];
    sm[threadIdx.x] = s;
    __syncthreads();
    for (int o = 64; o > 0; o >>= 1) {
        if (threadIdx.x < o) sm[threadIdx.x] += sm[threadIdx.x + o];
        __syncthreads();
    }
    if (threadIdx.x == 0) g_meanin[ch] = sm[0] * (1.f / NPIX);
}

// ================= launch 2: per-OC additive const =================
__global__ void k_addconst(const float* __restrict__ b0, const float* __restrict__ b1) {
    __shared__ float sm[256];
    int OC = blockIdx.x, tid = threadIdx.x;
    float s = 0.f;
    if (tid < CIN) s = g_Wsum[OC * CIN + tid] * g_meanin[tid];
    sm[tid] = s;
    __syncthreads();
    for (int o = 128; o > 0; o >>= 1) {
        if (tid < o) sm[tid] += sm[tid + o];
        __syncthreads();
    }
    if (tid == 0) g_add[OC] = (OC < 64) ? b0[OC] : sm[0] * b1[(OC - 64) >> 1];
}

// ================= launch 3: conv = implicit GEMM, M=128 N=96 per CTA, 2 CTAs/SM =================
// 1024 CTAs (512 px-tiles x 2 n-halves), 256 thr = 8 warps (4M x 2N), warp tile m32 x n48.
// 3 stages x 28KB, fragment double-buffer across ks.
__global__ __launch_bounds__(256, 2) void k_conv(float* __restrict__ out) {
    extern __shared__ __align__(1024) char smem[];
    const uint32_t sb = smem_u32(smem);
    const int tid = threadIdx.x;
    const int lane = tid & 31, warp = tid >> 5;
    const int wm = warp & 3, wn = warp >> 2;
    const int nh = blockIdx.x & 1;
    const int tile = blockIdx.x >> 1;
    const int y = tile >> 1, xb = (tile & 1) << 7;

    const int a_row = (lane & 7) + ((lane >> 3) & 1) * 8;
    const int a_ks  = lane >> 4;
    const int b_row = (lane & 7) + ((lane >> 4) << 3);
    const int b_ks  = (lane >> 3) & 1;

    const int am = tid >> 1;         // A row loaded by this thread (0..127)
    const int aq = (tid & 1) * 4;    // first 16B chunk (0 or 4)

    float acc[2][6][4];
#pragma unroll
    for (int t = 0; t < 2; t++)
#pragma unroll
        for (int g = 0; g < 6; g++)
#pragma unroll
            for (int q = 0; q < 4; q++) acc[t][g][q] = 0.f;

#define ISSUE(I, S)                                                                  \
    {                                                                                \
        int tap = (I) / 3, c = (I) % 3;                                              \
        int ky = tap / 3, kx = tap % 3;                                              \
        int gy = (y + ky + 255) & 255;                                               \
        int gx = (xb + am + kx + 255) & 255;                                         \
        size_t so = ((size_t)((c << 16) + (gy << 8) + gx)) * 128 + (size_t)(aq * 16);\
        _Pragma("unroll")                                                            \
        for (int j = 0; j < 4; j++) {                                                \
            uint32_t d = sb + (S) * STG + swz((uint32_t)(am * 128 + (aq + j) * 16)); \
            cpa16(d, (const char*)g_xh + so + j * 16);                               \
        }                                                                            \
        const char* bs = (const char*)g_Wh + (size_t)(I) * 24576 + nh * 12288;       \
        _Pragma("unroll")                                                            \
        for (int j = 0; j < 3; j++) {                                                \
            int off = (tid + 256 * j) * 16;                                          \
            cpa16(sb + (S) * STG + 16384 + off, bs + off);                           \
        }                                                                            \
        asm volatile("cp.async.commit_group;");                                      \
    }

#define LOADFRAG(KS, B)                                                              \
    {                                                                                \
        _Pragma("unroll")                                                            \
        for (int t = 0; t < 2; t++)                                                  \
            ldsm4(ah[B][t], Ab + swz((uint32_t)((wm * 32 + t * 16 + a_row) * 128 + (KS) * 32 + a_ks * 16))); \
        _Pragma("unroll")                                                            \
        for (int g = 0; g < 3; g++)                                                  \
            ldsm4(bh[B][g], Bb + swz((uint32_t)((wn * 48 + g * 16 + b_row) * 128 + (KS) * 32 + b_ks * 16))); \
    }

    ISSUE(0, 0);
    ISSUE(1, 1);

#pragma unroll 3
    for (int i = 0; i < NCHUNK; i++) {
        if (i < NCHUNK - 2) { asm volatile("cp.async.wait_group 1;" ::: "memory"); }
        else                { asm volatile("cp.async.wait_group 0;" ::: "memory"); }
        __syncthreads();
        if (i + 2 < NCHUNK) ISSUE(i + 2, (i + 2) % 3);

        const uint32_t Ab = sb + (i % 3) * STG;
        const uint32_t Bb = Ab + 16384;

        uint32_t ah[2][2][4], bh[2][3][4];
        LOADFRAG(0, 0);
#pragma unroll
        for (int ks = 0; ks < 4; ks++) {
            const int cur = ks & 1;
            if (ks < 3) LOADFRAG(ks + 1, cur ^ 1);
#pragma unroll
            for (int g = 0; g < 3; g++)
#pragma unroll
                for (int t = 0; t < 2; t++)
#pragma unroll
                    for (int h = 0; h < 2; h++)
                        mma16816(acc[t][g * 2 + h], ah[cur][t], bh[cur][g] + 2 * h);
        }
    }
#undef ISSUE
#undef LOADFRAG

    // ---- epilogue ----
    const int col = (lane & 3) * 2;
    const int rowq = lane >> 2;
#pragma unroll
    for (int t = 0; t < 2; t++) {
        int px0 = xb + wm * 32 + t * 16 + rowq;
        int px1 = px0 + 8;
#pragma unroll
        for (int nf = 0; nf < 6; nf++) {
            int n = nh * 96 + wn * 48 + nf * 8 + col;
            float g0 = __ldg(&g_add[n]), g1 = __ldg(&g_add[n + 1]);
            float v0 = acc[t][nf][0] + g0, v1 = acc[t][nf][1] + g1;
            float v2 = acc[t][nf][2] + g0, v3 = acc[t][nf][3] + g1;
            if (n < 64) {
                out[(size_t)n * NPIX + y * NN + px0]       = v0;
                out[(size_t)(n + 1) * NPIX + y * NN + px0] = v1;
                out[(size_t)n * NPIX + y * NN + px1]       = v2;
                out[(size_t)(n + 1) * NPIX + y * NN + px1] = v3;
            } else {
                int oco = (n - 64) >> 1;
                size_t base = (size_t)64 * NPIX + ((size_t)(oco * NN + y) * NN) * 2;
                *(float2*)&out[base + px0 * 2] = make_float2(v0, v1);
                *(float2*)&out[base + px1 * 2] = make_float2(v2, v3);
            }
        }
    }
}

// ---------------- launcher ----------------
extern "C" void kernel_launch(void* const* d_in, const int* in_sizes, int n_in,
                              void* d_out, int out_size) {
    const float* x0   = (const float*)d_in[0];
    const float* x1   = (const float*)d_in[1];
    const float* fil0 = (const float*)d_in[2];
    const float* fil1 = (const float*)d_in[3];
    const float* fil2 = (const float*)d_in[4];
    const float* w00  = (const float*)d_in[5];
    const float* w01  = (const float*)d_in[6];
    const float* w10  = (const float*)d_in[7];
    const float* w11  = (const float*)d_in[8];
    const float* b0   = (const float*)d_in[9];
    const float* b1   = (const float*)d_in[10];
    float* out = (float*)d_out;

    k_xpack<<<dim3(512, 4), 128>>>(x0, x1, fil0, fil1, fil2, w00, w01, w10, w11);
    k_meanred<<<CIN, 128>>>();
    k_addconst<<<COUT, 256>>>(b0, b1);

    const int dyn_smem = 3 * STG;  // 86016
    cudaFuncSetAttribute(k_conv, cudaFuncAttributeMaxDynamicSharedMemorySize, dyn_smem);
    k_conv<<<1024, 256, dyn_smem>>>(out);
}

// round 12
// speedup vs baseline: 1.4320x; 1.0991x over previous
#include <cuda_runtime.h>
#include <cuda_fp16.h>
#include <cstdint>

#define NN     256
#define NPIX   65536
#define CIN    192
#define COUT   192
#define NCHUNK 27
#define STG    28672          // stage: A 16K | B 12K

// ---------------- device scratch ----------------
__device__ float g_Wsum[COUT * CIN];
__device__ float g_meanin[CIN];
__device__ float g_add[COUT];
__device__ float g_psum[3 * 64 * 512];
__device__ __align__(1024) __half g_Wh[(size_t)NCHUNK * 12288];  // [chunk] 192x64 fp16 swizzled
__device__ __align__(16) uint32_t g_xh[(size_t)3 * NPIX * 32];   // [c][pix][k2] fp16 pairs

// ---------------- helpers ----------------
__device__ __forceinline__ uint32_t smem_u32(const void* p) {
    uint32_t a;
    asm("{ .reg .u64 t; cvta.to.shared.u64 t, %1; cvt.u32.u64 %0, t; }" : "=r"(a) : "l"(p));
    return a;
}
__device__ __forceinline__ uint32_t swz(uint32_t off) { return off ^ ((off >> 3) & 0x70); }
__device__ __forceinline__ void ldsm4(uint32_t* r, uint32_t addr) {
    asm volatile("ldmatrix.sync.aligned.m8n8.x4.shared.b16 {%0,%1,%2,%3}, [%4];"
                 : "=r"(r[0]), "=r"(r[1]), "=r"(r[2]), "=r"(r[3]) : "r"(addr));
}
__device__ __forceinline__ void mma16816(float* d, const uint32_t* a, const uint32_t* b) {
    asm volatile("mma.sync.aligned.m16n8k16.row.col.f32.f16.f16.f32 "
                 "{%0,%1,%2,%3}, {%4,%5,%6,%7}, {%8,%9}, {%0,%1,%2,%3};"
                 : "+f"(d[0]), "+f"(d[1]), "+f"(d[2]), "+f"(d[3])
                 : "r"(a[0]), "r"(a[1]), "r"(a[2]), "r"(a[3]), "r"(b[0]), "r"(b[1]));
}
__device__ __forceinline__ void cpa16(uint32_t dst, const void* src) {
    asm volatile("cp.async.cg.shared.global [%0], [%1], 16;" :: "r"(dst), "l"(src));
}

// ---------------- weight synthesis body ----------------
__device__ __forceinline__ void weights_body(int idx,
        const float* __restrict__ fil0, const float* __restrict__ fil1,
        const float* __restrict__ fil2, const float* __restrict__ w00,
        const float* __restrict__ w01, const float* __restrict__ w10,
        const float* __restrict__ w11) {
    int OC = idx / CIN, IC = idx % CIN;
    float acc[9];
#pragma unroll
    for (int t = 0; t < 9; t++) acc[t] = 0.f;
    if (OC < 64) {
        if (IC < 64) {
            for (int k = 0; k < 3; k++) {
                float c = w00[(OC * 64 + IC) * 3 + k];
#pragma unroll
                for (int t = 0; t < 9; t++) acc[t] += c * fil0[k * 9 + t];
            }
        } else {
            int ici = (IC - 64) >> 1, tin = (IC - 64) & 1;
            for (int k = 0; k < 6; k++) {
                float c = w10[(OC * 64 + ici) * 6 + k];
#pragma unroll
                for (int t = 0; t < 9; t++) acc[t] += c * fil1[(k * 9 + t) * 2 + tin];
            }
        }
    } else {
        int oco = (OC - 64) >> 1, tout = (OC - 64) & 1;
        if (IC < 64) {
            for (int k = 0; k < 6; k++) {
                float c = w01[(oco * 64 + IC) * 6 + k];
#pragma unroll
                for (int t = 0; t < 9; t++) acc[t] += c * fil1[(k * 9 + t) * 2 + tout];
            }
        } else {
            int ici = (IC - 64) >> 1, tin = (IC - 64) & 1;
            for (int k = 0; k < 12; k++) {
                float c = w11[(oco * 64 + ici) * 12 + k];
#pragma unroll
                for (int t = 0; t < 9; t++) acc[t] += c * fil2[((k * 9 + t) * 2 + tin) * 2 + tout];
            }
        }
    }
    float s = 0.f;
    int cg = IC >> 6, kk = IC & 63;
    uint32_t sw = swz((uint32_t)(OC * 128 + kk * 2)) >> 1;
#pragma unroll
    for (int t = 0; t < 9; t++) {
        s += acc[t];
        g_Wh[(size_t)(t * 3 + cg) * 12288 + sw] = __float2half_rn(acc[t]);
    }
    g_Wsum[idx] = s;
}

// ================= launch 0: x pack + weight synthesis (fused roles) =================
#define XS 36
__global__ void k_xpack(const float* __restrict__ x0, const float* __restrict__ x1,
                        const float* __restrict__ fil0, const float* __restrict__ fil1,
                        const float* __restrict__ fil2, const float* __restrict__ w00,
                        const float* __restrict__ w01, const float* __restrict__ w10,
                        const float* __restrict__ w11) {
    if (blockIdx.y == 3) {
        int idx = blockIdx.x * 128 + threadIdx.x;
        if (idx < COUT * CIN) weights_body(idx, fil0, fil1, fil2, w00, w01, w10, w11);
        return;
    }
    __shared__ uint32_t shh[128 * XS];
    __shared__ float red[64][2];
    const int c = blockIdx.y, tid = threadIdx.x;
    const int px = blockIdx.x * 128 + tid;
#pragma unroll 8
    for (int k2 = 0; k2 < 32; k2++) {
        float v0, v1;
        if (c == 0) {
            v0 = x0[(size_t)(2 * k2) * NPIX + px];
            v1 = x0[(size_t)(2 * k2 + 1) * NPIX + px];
        } else {
            int j = (c - 1) * 64 + 2 * k2;
            float2 p = *(const float2*)&x1[((size_t)(j >> 1) * NPIX + px) * 2];
            v0 = p.x; v1 = p.y;
        }
        __half h0 = __float2half_rn(v0), h1 = __float2half_rn(v1);
        shh[tid * XS + k2] = (uint32_t)__half_as_ushort(h0) | ((uint32_t)__half_as_ushort(h1) << 16);
    }
    __syncthreads();
#pragma unroll
    for (int r = 0; r < 8; r++) {
        int s = tid + 128 * r;
        int pl = s >> 3, q = s & 7;
        uint4 vh = *(const uint4*)&shh[pl * XS + q * 4];
        size_t o = ((size_t)c * NPIX + blockIdx.x * 128 + pl) * 32 + q * 4;
        *(uint4*)&g_xh[o] = vh;
    }
    {
        int ch = tid & 63, seg = tid >> 6;
        int k2 = ch >> 1, half = ch & 1;
        float s = 0.f;
        for (int p = 0; p < 64; p++) {
            uint32_t w = shh[(seg * 64 + p) * XS + k2];
            s += __half2float(__ushort_as_half((unsigned short)(half ? (w >> 16) : (w & 0xFFFF))));
        }
        red[ch][seg] = s;
        __syncthreads();
        if (tid < 64)
            g_psum[(c * 64 + tid) * 512 + blockIdx.x] = red[tid][0] + red[tid][1];
    }
}

// ================= launch 1: reduce channel means =================
__global__ void k_meanred() {
    __shared__ float sm[128];
    int ch = blockIdx.x;
    float s = 0.f;
    for (int i = threadIdx.x; i < 512; i += 128) s += g_psum[ch * 512 + i];
    sm[threadIdx.x] = s;
    __syncthreads();
    for (int o = 64; o > 0; o >>= 1) {
        if (threadIdx.x < o) sm[threadIdx.x] += sm[threadIdx.x + o];
        __syncthreads();
    }
    if (threadIdx.x == 0) g_meanin[ch] = sm[0] * (1.f / NPIX);
}

// ================= launch 2: per-OC additive const =================
__global__ void k_addconst(const float* __restrict__ b0, const float* __restrict__ b1) {
    __shared__ float sm[256];
    int OC = blockIdx.x, tid = threadIdx.x;
    float s = 0.f;
    if (tid < CIN) s = g_Wsum[OC * CIN + tid] * g_meanin[tid];
    sm[tid] = s;
    __syncthreads();
    for (int o = 128; o > 0; o >>= 1) {
        if (tid < o) sm[tid] += sm[tid + o];
        __syncthreads();
    }
    if (tid == 0) g_add[OC] = (OC < 64) ? b0[OC] : sm[0] * b1[(OC - 64) >> 1];
}

// ================= launch 3: conv — cross-chunk software pipeline =================
// 1024 CTAs, 256 thr = 8 warps (4M x 2N), warp tile m32 x n48, 3 stages, 2 CTAs/SM.
__global__ __launch_bounds__(256, 2) void k_conv(float* __restrict__ out) {
    extern __shared__ __align__(1024) char smem[];
    const uint32_t sb = smem_u32(smem);
    const int tid = threadIdx.x;
    const int lane = tid & 31, warp = tid >> 5;
    const int wm = warp & 3, wn = warp >> 2;
    const int nh = blockIdx.x & 1;
    const int tile = blockIdx.x >> 1;
    const int y = tile >> 1, xb = (tile & 1) << 7;

    const int a_row = (lane & 7) + ((lane >> 3) & 1) * 8;
    const int a_ks  = lane >> 4;
    const int b_row = (lane & 7) + ((lane >> 4) << 3);
    const int b_ks  = (lane >> 3) & 1;

    const int am = tid >> 1;
    const int aq = (tid & 1) * 4;

    float acc[2][6][4];
#pragma unroll
    for (int t = 0; t < 2; t++)
#pragma unroll
        for (int g = 0; g < 6; g++)
#pragma unroll
            for (int q = 0; q < 4; q++) acc[t][g][q] = 0.f;

    uint32_t ah[2][2][4], bh[2][3][4];

#define ISSUE(I, S)                                                                  \
    {                                                                                \
        int tap = (I) / 3, c = (I) % 3;                                              \
        int ky = tap / 3, kx = tap % 3;                                              \
        int gy = (y + ky + 255) & 255;                                               \
        int gx = (xb + am + kx + 255) & 255;                                         \
        size_t so = ((size_t)((c << 16) + (gy << 8) + gx)) * 128 + (size_t)(aq * 16);\
        _Pragma("unroll")                                                            \
        for (int j = 0; j < 4; j++) {                                                \
            uint32_t d = sb + (S) * STG + swz((uint32_t)(am * 128 + (aq + j) * 16)); \
            cpa16(d, (const char*)g_xh + so + j * 16);                               \
        }                                                                            \
        const char* bs = (const char*)g_Wh + (size_t)(I) * 24576 + nh * 12288;       \
        _Pragma("unroll")                                                            \
        for (int j = 0; j < 3; j++) {                                                \
            int off = (tid + 256 * j) * 16;                                          \
            cpa16(sb + (S) * STG + 16384 + off, bs + off);                           \
        }                                                                            \
        asm volatile("cp.async.commit_group;");                                      \
    }

#define LOADFRAG(STAGE, KS, B)                                                       \
    {                                                                                \
        const uint32_t Ab_ = sb + (STAGE) * STG;                                     \
        const uint32_t Bb_ = Ab_ + 16384;                                            \
        _Pragma("unroll")                                                            \
        for (int t = 0; t < 2; t++)                                                  \
            ldsm4(ah[B][t], Ab_ + swz((uint32_t)((wm * 32 + t * 16 + a_row) * 128 + (KS) * 32 + a_ks * 16))); \
        _Pragma("unroll")                                                            \
        for (int g = 0; g < 3; g++)                                                  \
            ldsm4(bh[B][g], Bb_ + swz((uint32_t)((wn * 48 + g * 16 + b_row) * 128 + (KS) * 32 + b_ks * 16))); \
    }

#define MMABLK(B)                                                                    \
    {                                                                                \
        _Pragma("unroll")                                                            \
        for (int g = 0; g < 3; g++)                                                  \
            _Pragma("unroll")                                                        \
            for (int t = 0; t < 2; t++)                                              \
                _Pragma("unroll")                                                    \
                for (int h = 0; h < 2; h++)                                          \
                    mma16816(acc[t][g * 2 + h], ah[B][t], bh[B][g] + 2 * h);         \
    }

    // ---- prologue ----
    ISSUE(0, 0);
    ISSUE(1, 1);
    asm volatile("cp.async.wait_group 1;" ::: "memory");   // chunk 0 resident
    __syncthreads();
    LOADFRAG(0, 0, 0);                                     // chunk 0, ks0 -> buf 0

#pragma unroll 3
    for (int i = 0; i < NCHUNK; i++) {
        const int stg = i % 3;
        // ks 0..2: MMA current buf, prefetch next ks frags
        LOADFRAG(stg, 1, 1);  MMABLK(0);
        LOADFRAG(stg, 2, 0);  MMABLK(1);
        LOADFRAG(stg, 3, 1);  MMABLK(0);
        // chunk boundary (hidden under the last MMA block)
        if (i + 2 < NCHUNK) {
            ISSUE(i + 2, (i + 2) % 3);
            asm volatile("cp.async.wait_group 1;" ::: "memory");   // chunk i+1 resident
            __syncthreads();
        } else if (i + 1 < NCHUNK) {
            asm volatile("cp.async.wait_group 0;" ::: "memory");
            __syncthreads();
        }
        if (i + 1 < NCHUNK) LOADFRAG((i + 1) % 3, 0, 0);   // next chunk ks0 -> buf 0
        MMABLK(1);                                          // ks3
    }
#undef ISSUE
#undef LOADFRAG
#undef MMABLK

    // ---- epilogue ----
    const int col = (lane & 3) * 2;
    const int rowq = lane >> 2;
#pragma unroll
    for (int t = 0; t < 2; t++) {
        int px0 = xb + wm * 32 + t * 16 + rowq;
        int px1 = px0 + 8;
#pragma unroll
        for (int nf = 0; nf < 6; nf++) {
            int n = nh * 96 + wn * 48 + nf * 8 + col;
            float g0 = __ldg(&g_add[n]), g1 = __ldg(&g_add[n + 1]);
            float v0 = acc[t][nf][0] + g0, v1 = acc[t][nf][1] + g1;
            float v2 = acc[t][nf][2] + g0, v3 = acc[t][nf][3] + g1;
            if (n < 64) {
                out[(size_t)n * NPIX + y * NN + px0]       = v0;
                out[(size_t)(n + 1) * NPIX + y * NN + px0] = v1;
                out[(size_t)n * NPIX + y * NN + px1]       = v2;
                out[(size_t)(n + 1) * NPIX + y * NN + px1] = v3;
            } else {
                int oco = (n - 64) >> 1;
                size_t base = (size_t)64 * NPIX + ((size_t)(oco * NN + y) * NN) * 2;
                *(float2*)&out[base + px0 * 2] = make_float2(v0, v1);
                *(float2*)&out[base + px1 * 2] = make_float2(v2, v3);
            }
        }
    }
}

// ---------------- launcher ----------------
extern "C" void kernel_launch(void* const* d_in, const int* in_sizes, int n_in,
                              void* d_out, int out_size) {
    const float* x0   = (const float*)d_in[0];
    const float* x1   = (const float*)d_in[1];
    const float* fil0 = (const float*)d_in[2];
    const float* fil1 = (const float*)d_in[3];
    const float* fil2 = (const float*)d_in[4];
    const float* w00  = (const float*)d_in[5];
    const float* w01  = (const float*)d_in[6];
    const float* w10  = (const float*)d_in[7];
    const float* w11  = (const float*)d_in[8];
    const float* b0   = (const float*)d_in[9];
    const float* b1   = (const float*)d_in[10];
    float* out = (float*)d_out;

    k_xpack<<<dim3(512, 4), 128>>>(x0, x1, fil0, fil1, fil2, w00, w01, w10, w11);
    k_meanred<<<CIN, 128>>>();
    k_addconst<<<COUT, 256>>>(b0, b1);

    const int dyn_smem = 3 * STG;  // 86016
    cudaFuncSetAttribute(k_conv, cudaFuncAttributeMaxDynamicSharedMemorySize, dyn_smem);
    k_conv<<<1024, 256, dyn_smem>>>(out);
}

// round 13
// speedup vs baseline: 1.4720x; 1.0279x over previous
#include <cuda_runtime.h>
#include <cuda_fp16.h>
#include <cstdint>

#define NN     256
#define NPIX   65536
#define CIN    192
#define COUT   192
#define NCHUNK 27
#define STG    40960          // stage: A 16K | B 24K

// ---------------- device scratch ----------------
__device__ float g_Wsum[COUT * CIN];
__device__ float g_meanin[CIN];
__device__ float g_add[COUT];
__device__ float g_psum[3 * 64 * 512];
__device__ __align__(1024) __half g_Wh[(size_t)NCHUNK * 12288];  // [chunk] 192x64 fp16 swizzled
__device__ __align__(16) uint32_t g_xh[(size_t)3 * NPIX * 32];   // [c][pix][k2] fp16 pairs

// ---------------- helpers ----------------
__device__ __forceinline__ uint32_t smem_u32(const void* p) {
    uint32_t a;
    asm("{ .reg .u64 t; cvta.to.shared.u64 t, %1; cvt.u32.u64 %0, t; }" : "=r"(a) : "l"(p));
    return a;
}
__device__ __forceinline__ uint32_t swz(uint32_t off) { return off ^ ((off >> 3) & 0x70); }
__device__ __forceinline__ void ldsm4(uint32_t* r, uint32_t addr) {
    asm volatile("ldmatrix.sync.aligned.m8n8.x4.shared.b16 {%0,%1,%2,%3}, [%4];"
                 : "=r"(r[0]), "=r"(r[1]), "=r"(r[2]), "=r"(r[3]) : "r"(addr));
}
__device__ __forceinline__ void mma16816(float* d, const uint32_t* a, const uint32_t* b) {
    asm volatile("mma.sync.aligned.m16n8k16.row.col.f32.f16.f16.f32 "
                 "{%0,%1,%2,%3}, {%4,%5,%6,%7}, {%8,%9}, {%0,%1,%2,%3};"
                 : "+f"(d[0]), "+f"(d[1]), "+f"(d[2]), "+f"(d[3])
                 : "r"(a[0]), "r"(a[1]), "r"(a[2]), "r"(a[3]), "r"(b[0]), "r"(b[1]));
}
__device__ __forceinline__ void cpa16(uint32_t dst, const void* src) {
    asm volatile("cp.async.cg.shared.global [%0], [%1], 16;" :: "r"(dst), "l"(src));
}

// ---------------- weight synthesis body ----------------
__device__ __forceinline__ void weights_body(int idx,
        const float* __restrict__ fil0, const float* __restrict__ fil1,
        const float* __restrict__ fil2, const float* __restrict__ w00,
        const float* __restrict__ w01, const float* __restrict__ w10,
        const float* __restrict__ w11) {
    int OC = idx / CIN, IC = idx % CIN;
    float acc[9];
#pragma unroll
    for (int t = 0; t < 9; t++) acc[t] = 0.f;
    if (OC < 64) {
        if (IC < 64) {
            for (int k = 0; k < 3; k++) {
                float c = w00[(OC * 64 + IC) * 3 + k];
#pragma unroll
                for (int t = 0; t < 9; t++) acc[t] += c * fil0[k * 9 + t];
            }
        } else {
            int ici = (IC - 64) >> 1, tin = (IC - 64) & 1;
            for (int k = 0; k < 6; k++) {
                float c = w10[(OC * 64 + ici) * 6 + k];
#pragma unroll
                for (int t = 0; t < 9; t++) acc[t] += c * fil1[(k * 9 + t) * 2 + tin];
            }
        }
    } else {
        int oco = (OC - 64) >> 1, tout = (OC - 64) & 1;
        if (IC < 64) {
            for (int k = 0; k < 6; k++) {
                float c = w01[(oco * 64 + IC) * 6 + k];
#pragma unroll
                for (int t = 0; t < 9; t++) acc[t] += c * fil1[(k * 9 + t) * 2 + tout];
            }
        } else {
            int ici = (IC - 64) >> 1, tin = (IC - 64) & 1;
            for (int k = 0; k < 12; k++) {
                float c = w11[(oco * 64 + ici) * 12 + k];
#pragma unroll
                for (int t = 0; t < 9; t++) acc[t] += c * fil2[((k * 9 + t) * 2 + tin) * 2 + tout];
            }
        }
    }
    float s = 0.f;
    int cg = IC >> 6, kk = IC & 63;
    uint32_t sw = swz((uint32_t)(OC * 128 + kk * 2)) >> 1;
#pragma unroll
    for (int t = 0; t < 9; t++) {
        s += acc[t];
        g_Wh[(size_t)(t * 3 + cg) * 12288 + sw] = __float2half_rn(acc[t]);
    }
    g_Wsum[idx] = s;
}

// ================= launch 0: x pack + weight synthesis (fused roles) =================
#define XS 36
__global__ void k_xpack(const float* __restrict__ x0, const float* __restrict__ x1,
                        const float* __restrict__ fil0, const float* __restrict__ fil1,
                        const float* __restrict__ fil2, const float* __restrict__ w00,
                        const float* __restrict__ w01, const float* __restrict__ w10,
                        const float* __restrict__ w11) {
    if (blockIdx.y == 3) {
        int idx = blockIdx.x * 128 + threadIdx.x;
        if (idx < COUT * CIN) weights_body(idx, fil0, fil1, fil2, w00, w01, w10, w11);
        return;
    }
    __shared__ uint32_t shh[128 * XS];
    __shared__ float red[64][2];
    const int c = blockIdx.y, tid = threadIdx.x;
    const int px = blockIdx.x * 128 + tid;
#pragma unroll 8
    for (int k2 = 0; k2 < 32; k2++) {
        float v0, v1;
        if (c == 0) {
            v0 = x0[(size_t)(2 * k2) * NPIX + px];
            v1 = x0[(size_t)(2 * k2 + 1) * NPIX + px];
        } else {
            int j = (c - 1) * 64 + 2 * k2;
            float2 p = *(const float2*)&x1[((size_t)(j >> 1) * NPIX + px) * 2];
            v0 = p.x; v1 = p.y;
        }
        __half h0 = __float2half_rn(v0), h1 = __float2half_rn(v1);
        shh[tid * XS + k2] = (uint32_t)__half_as_ushort(h0) | ((uint32_t)__half_as_ushort(h1) << 16);
    }
    __syncthreads();
#pragma unroll
    for (int r = 0; r < 8; r++) {
        int s = tid + 128 * r;
        int pl = s >> 3, q = s & 7;
        uint4 vh = *(const uint4*)&shh[pl * XS + q * 4];
        size_t o = ((size_t)c * NPIX + blockIdx.x * 128 + pl) * 32 + q * 4;
        *(uint4*)&g_xh[o] = vh;
    }
    {
        int ch = tid & 63, seg = tid >> 6;
        int k2 = ch >> 1, half = ch & 1;
        float s = 0.f;
        for (int p = 0; p < 64; p++) {
            uint32_t w = shh[(seg * 64 + p) * XS + k2];
            s += __half2float(__ushort_as_half((unsigned short)(half ? (w >> 16) : (w & 0xFFFF))));
        }
        red[ch][seg] = s;
        __syncthreads();
        if (tid < 64)
            g_psum[(c * 64 + tid) * 512 + blockIdx.x] = red[tid][0] + red[tid][1];
    }
}

// ================= launch 1: reduce channel means =================
__global__ void k_meanred() {
    __shared__ float sm[128];
    int ch = blockIdx.x;
    float s = 0.f;
    for (int i = threadIdx.x; i < 512; i += 128) s += g_psum[ch * 512 + i];
    sm[threadIdx.x] = s;
    __syncthreads();
    for (int o = 64; o > 0; o >>= 1) {
        if (threadIdx.x < o) sm[threadIdx.x] += sm[threadIdx.x + o];
        __syncthreads();
    }
    if (threadIdx.x == 0) g_meanin[ch] = sm[0] * (1.f / NPIX);
}

// ================= launch 2: per-OC additive const =================
__global__ void k_addconst(const float* __restrict__ b0, const float* __restrict__ b1) {
    __shared__ float sm[256];
    int OC = blockIdx.x, tid = threadIdx.x;
    float s = 0.f;
    if (tid < CIN) s = g_Wsum[OC * CIN + tid] * g_meanin[tid];
    sm[tid] = s;
    __syncthreads();
    for (int o = 128; o > 0; o >>= 1) {
        if (tid < o) sm[tid] += sm[tid + o];
        __syncthreads();
    }
    if (tid == 0) g_add[OC] = (OC < 64) ? b0[OC] : sm[0] * b1[(OC - 64) >> 1];
}

// ================= launch 3: conv — M=128 N=192, 16 warps 4Mx4N, cross-chunk pipeline =================
// 512 CTAs (128 px each), 512 thr, warp tile m32 x n48, 3 stages x 40KB, 1 CTA/SM.
__global__ __launch_bounds__(512, 1) void k_conv(float* __restrict__ out) {
    extern __shared__ __align__(1024) char smem[];
    const uint32_t sb = smem_u32(smem);
    const int tid = threadIdx.x;
    const int lane = tid & 31, warp = tid >> 5;
    const int wm = warp & 3, wn = warp >> 2;
    const int y = blockIdx.x >> 1, xb = (blockIdx.x & 1) << 7;

    const int a_row = (lane & 7) + ((lane >> 3) & 1) * 8;
    const int a_ks  = lane >> 4;
    const int b_row = (lane & 7) + ((lane >> 4) << 3);
    const int b_ks  = (lane >> 3) & 1;

    const int am = tid >> 2;         // A row loaded by this thread (0..127)
    const int aq = (tid & 3) * 2;    // first 16B chunk (0,2,4,6)

    float acc[2][6][4];
#pragma unroll
    for (int t = 0; t < 2; t++)
#pragma unroll
        for (int g = 0; g < 6; g++)
#pragma unroll
            for (int q = 0; q < 4; q++) acc[t][g][q] = 0.f;

    uint32_t ah[2][2][4], bh[2][3][4];

#define ISSUE(I, S)                                                                  \
    {                                                                                \
        int tap = (I) / 3, c = (I) % 3;                                              \
        int ky = tap / 3, kx = tap % 3;                                              \
        int gy = (y + ky + 255) & 255;                                               \
        int gx = (xb + am + kx + 255) & 255;                                         \
        size_t so = ((size_t)((c << 16) + (gy << 8) + gx)) * 128 + (size_t)(aq * 16);\
        _Pragma("unroll")                                                            \
        for (int j = 0; j < 2; j++) {                                                \
            uint32_t d = sb + (S) * STG + swz((uint32_t)(am * 128 + (aq + j) * 16)); \
            cpa16(d, (const char*)g_xh + so + j * 16);                               \
        }                                                                            \
        const char* bs = (const char*)g_Wh + (size_t)(I) * 24576;                    \
        _Pragma("unroll")                                                            \
        for (int j = 0; j < 3; j++) {                                                \
            int off = (tid + 512 * j) * 16;                                          \
            cpa16(sb + (S) * STG + 16384 + off, bs + off);                           \
        }                                                                            \
        asm volatile("cp.async.commit_group;");                                      \
    }

#define LOADFRAG(STAGE, KS, B)                                                       \
    {                                                                                \
        const uint32_t Ab_ = sb + (STAGE) * STG;                                     \
        const uint32_t Bb_ = Ab_ + 16384;                                            \
        _Pragma("unroll")                                                            \
        for (int t = 0; t < 2; t++)                                                  \
            ldsm4(ah[B][t], Ab_ + swz((uint32_t)((wm * 32 + t * 16 + a_row) * 128 + (KS) * 32 + a_ks * 16))); \
        _Pragma("unroll")                                                            \
        for (int g = 0; g < 3; g++)                                                  \
            ldsm4(bh[B][g], Bb_ + swz((uint32_t)((wn * 48 + g * 16 + b_row) * 128 + (KS) * 32 + b_ks * 16))); \
    }

#define MMABLK(B)                                                                    \
    {                                                                                \
        _Pragma("unroll")                                                            \
        for (int g = 0; g < 3; g++)                                                  \
            _Pragma("unroll")                                                        \
            for (int t = 0; t < 2; t++)                                              \
                _Pragma("unroll")                                                    \
                for (int h = 0; h < 2; h++)                                          \
                    mma16816(acc[t][g * 2 + h], ah[B][t], bh[B][g] + 2 * h);         \
    }

    // ---- prologue ----
    ISSUE(0, 0);
    ISSUE(1, 1);
    asm volatile("cp.async.wait_group 1;" ::: "memory");
    __syncthreads();
    LOADFRAG(0, 0, 0);

#pragma unroll 3
    for (int i = 0; i < NCHUNK; i++) {
        const int stg = i % 3;
        LOADFRAG(stg, 1, 1);  MMABLK(0);
        LOADFRAG(stg, 2, 0);  MMABLK(1);
        LOADFRAG(stg, 3, 1);  MMABLK(0);
        if (i + 2 < NCHUNK) {
            ISSUE(i + 2, (i + 2) % 3);
            asm volatile("cp.async.wait_group 1;" ::: "memory");
            __syncthreads();
        } else if (i + 1 < NCHUNK) {
            asm volatile("cp.async.wait_group 0;" ::: "memory");
            __syncthreads();
        }
        if (i + 1 < NCHUNK) LOADFRAG((i + 1) % 3, 0, 0);
        MMABLK(1);
    }
#undef ISSUE
#undef LOADFRAG
#undef MMABLK

    // ---- epilogue ----
    const int col = (lane & 3) * 2;
    const int rowq = lane >> 2;
#pragma unroll
    for (int t = 0; t < 2; t++) {
        int px0 = xb + wm * 32 + t * 16 + rowq;
        int px1 = px0 + 8;
#pragma unroll
        for (int nf = 0; nf < 6; nf++) {
            int n = wn * 48 + nf * 8 + col;
            float g0 = __ldg(&g_add[n]), g1 = __ldg(&g_add[n + 1]);
            float v0 = acc[t][nf][0] + g0, v1 = acc[t][nf][1] + g1;
            float v2 = acc[t][nf][2] + g0, v3 = acc[t][nf][3] + g1;
            if (n < 64) {
                out[(size_t)n * NPIX + y * NN + px0]       = v0;
                out[(size_t)(n + 1) * NPIX + y * NN + px0] = v1;
                out[(size_t)n * NPIX + y * NN + px1]       = v2;
                out[(size_t)(n + 1) * NPIX + y * NN + px1] = v3;
            } else {
                int oco = (n - 64) >> 1;
                size_t base = (size_t)64 * NPIX + ((size_t)(oco * NN + y) * NN) * 2;
                *(float2*)&out[base + px0 * 2] = make_float2(v0, v1);
                *(float2*)&out[base + px1 * 2] = make_float2(v2, v3);
            }
        }
    }
}

// ---------------- launcher ----------------
extern "C" void kernel_launch(void* const* d_in, const int* in_sizes, int n_in,
                              void* d_out, int out_size) {
    const float* x0   = (const float*)d_in[0];
    const float* x1   = (const float*)d_in[1];
    const float* fil0 = (const float*)d_in[2];
    const float* fil1 = (const float*)d_in[3];
    const float* fil2 = (const float*)d_in[4];
    const float* w00  = (const float*)d_in[5];
    const float* w01  = (const float*)d_in[6];
    const float* w10  = (const float*)d_in[7];
    const float* w11  = (const float*)d_in[8];
    const float* b0   = (const float*)d_in[9];
    const float* b1   = (const float*)d_in[10];
    float* out = (float*)d_out;

    k_xpack<<<dim3(512, 4), 128>>>(x0, x1, fil0, fil1, fil2, w00, w01, w10, w11);
    k_meanred<<<CIN, 128>>>();
    k_addconst<<<COUT, 256>>>(b0, b1);

    const int dyn_smem = 3 * STG;  // 122880
    cudaFuncSetAttribute(k_conv, cudaFuncAttributeMaxDynamicSharedMemorySize, dyn_smem);
    k_conv<<<512, 512, dyn_smem>>>(out);
}

// round 14
// speedup vs baseline: 1.6197x; 1.1004x over previous
#include <cuda_runtime.h>
#include <cuda_fp16.h>
#include <cstdint>

#define NN     256
#define NPIX   65536
#define CIN    192
#define COUT   192
#define NCHUNK 27
#define STG    32768          // stage: A 8K | B 24K

// ---------------- device scratch ----------------
__device__ float g_Wsum[COUT * CIN];
__device__ float g_meanin[CIN];
__device__ float g_add[COUT];
__device__ float g_psum[3 * 64 * 512];
__device__ __align__(1024) __half g_Wh[(size_t)NCHUNK * 12288];  // [chunk] 192x64 fp16 swizzled
__device__ __align__(16) uint32_t g_xh[(size_t)3 * NPIX * 32];   // [c][pix][k2] fp16 pairs

// ---------------- helpers ----------------
__device__ __forceinline__ uint32_t smem_u32(const void* p) {
    uint32_t a;
    asm("{ .reg .u64 t; cvta.to.shared.u64 t, %1; cvt.u32.u64 %0, t; }" : "=r"(a) : "l"(p));
    return a;
}
__device__ __forceinline__ uint32_t swz(uint32_t off) { return off ^ ((off >> 3) & 0x70); }
__device__ __forceinline__ void ldsm4(uint32_t* r, uint32_t addr) {
    asm volatile("ldmatrix.sync.aligned.m8n8.x4.shared.b16 {%0,%1,%2,%3}, [%4];"
                 : "=r"(r[0]), "=r"(r[1]), "=r"(r[2]), "=r"(r[3]) : "r"(addr));
}
__device__ __forceinline__ void mma16816(float* d, const uint32_t* a, const uint32_t* b) {
    asm volatile("mma.sync.aligned.m16n8k16.row.col.f32.f16.f16.f32 "
                 "{%0,%1,%2,%3}, {%4,%5,%6,%7}, {%8,%9}, {%0,%1,%2,%3};"
                 : "+f"(d[0]), "+f"(d[1]), "+f"(d[2]), "+f"(d[3])
                 : "r"(a[0]), "r"(a[1]), "r"(a[2]), "r"(a[3]), "r"(b[0]), "r"(b[1]));
}
__device__ __forceinline__ void cpa16(uint32_t dst, const void* src) {
    asm volatile("cp.async.cg.shared.global [%0], [%1], 16;" :: "r"(dst), "l"(src));
}

// ---------------- weight synthesis body ----------------
__device__ __forceinline__ void weights_body(int idx,
        const float* __restrict__ fil0, const float* __restrict__ fil1,
        const float* __restrict__ fil2, const float* __restrict__ w00,
        const float* __restrict__ w01, const float* __restrict__ w10,
        const float* __restrict__ w11) {
    int OC = idx / CIN, IC = idx % CIN;
    float acc[9];
#pragma unroll
    for (int t = 0; t < 9; t++) acc[t] = 0.f;
    if (OC < 64) {
        if (IC < 64) {
            for (int k = 0; k < 3; k++) {
                float c = w00[(OC * 64 + IC) * 3 + k];
#pragma unroll
                for (int t = 0; t < 9; t++) acc[t] += c * fil0[k * 9 + t];
            }
        } else {
            int ici = (IC - 64) >> 1, tin = (IC - 64) & 1;
            for (int k = 0; k < 6; k++) {
                float c = w10[(OC * 64 + ici) * 6 + k];
#pragma unroll
                for (int t = 0; t < 9; t++) acc[t] += c * fil1[(k * 9 + t) * 2 + tin];
            }
        }
    } else {
        int oco = (OC - 64) >> 1, tout = (OC - 64) & 1;
        if (IC < 64) {
            for (int k = 0; k < 6; k++) {
                float c = w01[(oco * 64 + IC) * 6 + k];
#pragma unroll
                for (int t = 0; t < 9; t++) acc[t] += c * fil1[(k * 9 + t) * 2 + tout];
            }
        } else {
            int ici = (IC - 64) >> 1, tin = (IC - 64) & 1;
            for (int k = 0; k < 12; k++) {
                float c = w11[(oco * 64 + ici) * 12 + k];
#pragma unroll
                for (int t = 0; t < 9; t++) acc[t] += c * fil2[((k * 9 + t) * 2 + tin) * 2 + tout];
            }
        }
    }
    float s = 0.f;
    int cg = IC >> 6, kk = IC & 63;
    uint32_t sw = swz((uint32_t)(OC * 128 + kk * 2)) >> 1;
#pragma unroll
    for (int t = 0; t < 9; t++) {
        s += acc[t];
        g_Wh[(size_t)(t * 3 + cg) * 12288 + sw] = __float2half_rn(acc[t]);
    }
    g_Wsum[idx] = s;
}

// ================= launch 0: x pack + weight synthesis (fused roles) =================
#define XS 36
__global__ void k_xpack(const float* __restrict__ x0, const float* __restrict__ x1,
                        const float* __restrict__ fil0, const float* __restrict__ fil1,
                        const float* __restrict__ fil2, const float* __restrict__ w00,
                        const float* __restrict__ w01, const float* __restrict__ w10,
                        const float* __restrict__ w11) {
    if (blockIdx.y == 3) {
        int idx = blockIdx.x * 128 + threadIdx.x;
        if (idx < COUT * CIN) weights_body(idx, fil0, fil1, fil2, w00, w01, w10, w11);
        return;
    }
    __shared__ uint32_t shh[128 * XS];
    __shared__ float red[64][2];
    const int c = blockIdx.y, tid = threadIdx.x;
    const int px = blockIdx.x * 128 + tid;
#pragma unroll 8
    for (int k2 = 0; k2 < 32; k2++) {
        float v0, v1;
        if (c == 0) {
            v0 = x0[(size_t)(2 * k2) * NPIX + px];
            v1 = x0[(size_t)(2 * k2 + 1) * NPIX + px];
        } else {
            int j = (c - 1) * 64 + 2 * k2;
            float2 p = *(const float2*)&x1[((size_t)(j >> 1) * NPIX + px) * 2];
            v0 = p.x; v1 = p.y;
        }
        __half h0 = __float2half_rn(v0), h1 = __float2half_rn(v1);
        shh[tid * XS + k2] = (uint32_t)__half_as_ushort(h0) | ((uint32_t)__half_as_ushort(h1) << 16);
    }
    __syncthreads();
#pragma unroll
    for (int r = 0; r < 8; r++) {
        int s = tid + 128 * r;
        int pl = s >> 3, q = s & 7;
        uint4 vh = *(const uint4*)&shh[pl * XS + q * 4];
        size_t o = ((size_t)c * NPIX + blockIdx.x * 128 + pl) * 32 + q * 4;
        *(uint4*)&g_xh[o] = vh;
    }
    {
        int ch = tid & 63, seg = tid >> 6;
        int k2 = ch >> 1, half = ch & 1;
        float s = 0.f;
        for (int p = 0; p < 64; p++) {
            uint32_t w = shh[(seg * 64 + p) * XS + k2];
            s += __half2float(__ushort_as_half((unsigned short)(half ? (w >> 16) : (w & 0xFFFF))));
        }
        red[ch][seg] = s;
        __syncthreads();
        if (tid < 64)
            g_psum[(c * 64 + tid) * 512 + blockIdx.x] = red[tid][0] + red[tid][1];
    }
}

// ================= launch 1: reduce channel means =================
__global__ void k_meanred() {
    __shared__ float sm[128];
    int ch = blockIdx.x;
    float s = 0.f;
    for (int i = threadIdx.x; i < 512; i += 128) s += g_psum[ch * 512 + i];
    sm[threadIdx.x] = s;
    __syncthreads();
    for (int o = 64; o > 0; o >>= 1) {
        if (threadIdx.x < o) sm[threadIdx.x] += sm[threadIdx.x + o];
        __syncthreads();
    }
    if (threadIdx.x == 0) g_meanin[ch] = sm[0] * (1.f / NPIX);
}

// ================= launch 2: per-OC additive const =================
__global__ void k_addconst(const float* __restrict__ b0, const float* __restrict__ b1) {
    __shared__ float sm[256];
    int OC = blockIdx.x, tid = threadIdx.x;
    float s = 0.f;
    if (tid < CIN) s = g_Wsum[OC * CIN + tid] * g_meanin[tid];
    sm[tid] = s;
    __syncthreads();
    for (int o = 128; o > 0; o >>= 1) {
        if (tid < o) sm[tid] += sm[tid + o];
        __syncthreads();
    }
    if (tid == 0) g_add[OC] = (OC < 64) ? b0[OC] : sm[0] * b1[(OC - 64) >> 1];
}

// ================= launch 3: conv — M=64 N=192 tiles, 2 CTAs/SM, cross-chunk pipeline =================
// 1024 CTAs (64 px each), 256 thr = 8 warps (2M x 4N), warp tile m32 x n48, 3 stages x 32KB.
__global__ __launch_bounds__(256, 2) void k_conv(float* __restrict__ out) {
    extern __shared__ __align__(1024) char smem[];
    const uint32_t sb = smem_u32(smem);
    const int tid = threadIdx.x;
    const int lane = tid & 31, warp = tid >> 5;
    const int wm = warp & 1, wn = warp >> 1;
    const int y = blockIdx.x >> 2, xb = (blockIdx.x & 3) << 6;

    const int a_row = (lane & 7) + ((lane >> 3) & 1) * 8;
    const int a_ks  = lane >> 4;
    const int b_row = (lane & 7) + ((lane >> 4) << 3);
    const int b_ks  = (lane >> 3) & 1;

    const int am = tid >> 2;         // A row loaded by this thread (0..63)
    const int aq = (tid & 3) * 2;    // first 16B chunk (0,2,4,6)

    float acc[2][6][4];
#pragma unroll
    for (int t = 0; t < 2; t++)
#pragma unroll
        for (int g = 0; g < 6; g++)
#pragma unroll
            for (int q = 0; q < 4; q++) acc[t][g][q] = 0.f;

    uint32_t ah[2][2][4], bh[2][3][4];

#define ISSUE(I, S)                                                                  \
    {                                                                                \
        int tap = (I) / 3, c = (I) % 3;                                              \
        int ky = tap / 3, kx = tap % 3;                                              \
        int gy = (y + ky + 255) & 255;                                               \
        int gx = (xb + am + kx + 255) & 255;                                         \
        size_t so = ((size_t)((c << 16) + (gy << 8) + gx)) * 128 + (size_t)(aq * 16);\
        _Pragma("unroll")                                                            \
        for (int j = 0; j < 2; j++) {                                                \
            uint32_t d = sb + (S) * STG + swz((uint32_t)(am * 128 + (aq + j) * 16)); \
            cpa16(d, (const char*)g_xh + so + j * 16);                               \
        }                                                                            \
        const char* bs = (const char*)g_Wh + (size_t)(I) * 24576;                    \
        _Pragma("unroll")                                                            \
        for (int j = 0; j < 6; j++) {                                                \
            int off = (tid + 256 * j) * 16;                                          \
            cpa16(sb + (S) * STG + 8192 + off, bs + off);                            \
        }                                                                            \
        asm volatile("cp.async.commit_group;");                                      \
    }

#define LOADFRAG(STAGE, KS, B)                                                       \
    {                                                                                \
        const uint32_t Ab_ = sb + (STAGE) * STG;                                     \
        const uint32_t Bb_ = Ab_ + 8192;                                             \
        _Pragma("unroll")                                                            \
        for (int t = 0; t < 2; t++)                                                  \
            ldsm4(ah[B][t], Ab_ + swz((uint32_t)((wm * 32 + t * 16 + a_row) * 128 + (KS) * 32 + a_ks * 16))); \
        _Pragma("unroll")                                                            \
        for (int g = 0; g < 3; g++)                                                  \
            ldsm4(bh[B][g], Bb_ + swz((uint32_t)((wn * 48 + g * 16 + b_row) * 128 + (KS) * 32 + b_ks * 16))); \
    }

#define MMABLK(B)                                                                    \
    {                                                                                \
        _Pragma("unroll")                                                            \
        for (int g = 0; g < 3; g++)                                                  \
            _Pragma("unroll")                                                        \
            for (int t = 0; t < 2; t++)                                              \
                _Pragma("unroll")                                                    \
                for (int h = 0; h < 2; h++)                                          \
                    mma16816(acc[t][g * 2 + h], ah[B][t], bh[B][g] + 2 * h);         \
    }

    // ---- prologue ----
    ISSUE(0, 0);
    ISSUE(1, 1);
    asm volatile("cp.async.wait_group 1;" ::: "memory");
    __syncthreads();
    LOADFRAG(0, 0, 0);

#pragma unroll 3
    for (int i = 0; i < NCHUNK; i++) {
        const int stg = i % 3;
        LOADFRAG(stg, 1, 1);  MMABLK(0);
        LOADFRAG(stg, 2, 0);  MMABLK(1);
        LOADFRAG(stg, 3, 1);  MMABLK(0);
        if (i + 2 < NCHUNK) {
            ISSUE(i + 2, (i + 2) % 3);
            asm volatile("cp.async.wait_group 1;" ::: "memory");
            __syncthreads();
        } else if (i + 1 < NCHUNK) {
            asm volatile("cp.async.wait_group 0;" ::: "memory");
            __syncthreads();
        }
        if (i + 1 < NCHUNK) LOADFRAG((i + 1) % 3, 0, 0);
        MMABLK(1);
    }
#undef ISSUE
#undef LOADFRAG
#undef MMABLK

    // ---- epilogue ----
    const int col = (lane & 3) * 2;
    const int rowq = lane >> 2;
#pragma unroll
    for (int t = 0; t < 2; t++) {
        int px0 = xb + wm * 32 + t * 16 + rowq;
        int px1 = px0 + 8;
#pragma unroll
        for (int nf = 0; nf < 6; nf++) {
            int n = wn * 48 + nf * 8 + col;
            float g0 = __ldg(&g_add[n]), g1 = __ldg(&g_add[n + 1]);
            float v0 = acc[t][nf][0] + g0, v1 = acc[t][nf][1] + g1;
            float v2 = acc[t][nf][2] + g0, v3 = acc[t][nf][3] + g1;
            if (n < 64) {
                out[(size_t)n * NPIX + y * NN + px0]       = v0;
                out[(size_t)(n + 1) * NPIX + y * NN + px0] = v1;
                out[(size_t)n * NPIX + y * NN + px1]       = v2;
                out[(size_t)(n + 1) * NPIX + y * NN + px1] = v3;
            } else {
                int oco = (n - 64) >> 1;
                size_t base = (size_t)64 * NPIX + ((size_t)(oco * NN + y) * NN) * 2;
                *(float2*)&out[base + px0 * 2] = make_float2(v0, v1);
                *(float2*)&out[base + px1 * 2] = make_float2(v2, v3);
            }
        }
    }
}

// ---------------- launcher ----------------
extern "C" void kernel_launch(void* const* d_in, const int* in_sizes, int n_in,
                              void* d_out, int out_size) {
    const float* x0   = (const float*)d_in[0];
    const float* x1   = (const float*)d_in[1];
    const float* fil0 = (const float*)d_in[2];
    const float* fil1 = (const float*)d_in[3];
    const float* fil2 = (const float*)d_in[4];
    const float* w00  = (const float*)d_in[5];
    const float* w01  = (const float*)d_in[6];
    const float* w10  = (const float*)d_in[7];
    const float* w11  = (const float*)d_in[8];
    const float* b0   = (const float*)d_in[9];
    const float* b1   = (const float*)d_in[10];
    float* out = (float*)d_out;

    k_xpack<<<dim3(512, 4), 128>>>(x0, x1, fil0, fil1, fil2, w00, w01, w10, w11);
    k_meanred<<<CIN, 128>>>();
    k_addconst<<<COUT, 256>>>(b0, b1);

    const int dyn_smem = 3 * STG;  // 98304
    cudaFuncSetAttribute(k_conv, cudaFuncAttributeMaxDynamicSharedMemorySize, dyn_smem);
    k_conv<<<1024, 256, dyn_smem>>>(out);
}